// round 11
// baseline (speedup 1.0000x reference)
#include <cuda_runtime.h>

typedef unsigned long long u64;

static constexpr int Bb = 16;
static constexpr int CE = 1024;
static constexpr int Tt = 2048;
static constexpr int CC = 64;
static constexpr int Kk = 4096;

static constexpr long long O_CODES = 0;
static constexpr long long O_QUANT = 32768;
static constexpr long long N_QUANT = (long long)Bb * CE * Tt;    // 33554432
static constexpr long long O_CBL   = O_QUANT + N_QUANT;           // 33587200
static constexpr long long O_CML   = O_CBL + 1;
static constexpr long long O_XPROJ = O_CML + 1;                   // 33587202 (even -> 8B aligned)
static constexpr long long N_XP    = (long long)Bb * CC * Tt;     // 2097152
static constexpr long long O_QPROJ = O_XPROJ + N_XP;              // 35684354 (even)

// scratch (static device globals; no runtime allocation)
__device__ __align__(16) float  g_Win[CC * CE];
__device__ __align__(16) float  g_Wout[CE * CC];
__device__ __align__(16) float  g_cbT[CC * Kk];    // (-2 * normalized codebook), [o][k]
__device__ __align__(16) float  g_cbn2[Kk];        // ||cb_n||^2
__device__ double g_lpart[256];

__device__ __forceinline__ u64 pk2(float lo, float hi) {
    u64 r; asm("mov.b64 %0, {%1, %2};" : "=l"(r) : "f"(lo), "f"(hi)); return r;
}
__device__ __forceinline__ float2 upk2(u64 v) {
    float2 r; asm("mov.b64 {%0, %1}, %2;" : "=f"(r.x), "=f"(r.y) : "l"(v)); return r;
}
__device__ __forceinline__ void fma2(u64 &d, u64 a, u64 b) {
    asm("fma.rn.f32x2 %0, %1, %2, %0;" : "+l"(d) : "l"(a), "l"(b));
}
__device__ __forceinline__ unsigned s2u(const void* p) {
    return (unsigned)__cvta_generic_to_shared(p);
}
__device__ __forceinline__ void cp16(unsigned s, const void* g) {
    asm volatile("cp.async.cg.shared.global [%0], [%1], 16;" :: "r"(s), "l"(g));
}
__device__ __forceinline__ void cpcommit() { asm volatile("cp.async.commit_group;"); }
__device__ __forceinline__ void cpwait1()  { asm volatile("cp.async.wait_group 1;"); }

// ---------------- prep: weight-norm W_in (rows of 1024) ----------------
__global__ __launch_bounds__(256) void k_prep_win(const float* __restrict__ v_in,
                                                  const float* __restrict__ g_in)
{
    __shared__ float sb[256];
    __shared__ float snorm;
    int o = blockIdx.x, tid = threadIdx.x;
    float s = 0.f;
#pragma unroll
    for (int j = 0; j < 4; j++) { float v = v_in[o * CE + tid + j * 256]; s += v * v; }
    sb[tid] = s; __syncthreads();
    for (int off = 128; off > 0; off >>= 1) { if (tid < off) sb[tid] += sb[tid + off]; __syncthreads(); }
    if (tid == 0) snorm = __fsqrt_rn(sb[0]);
    __syncthreads();
    float n = snorm, g = g_in[o];
#pragma unroll
    for (int j = 0; j < 4; j++) {
        int i = tid + j * 256;
        g_Win[o * CE + i] = __fdiv_rn(g * v_in[o * CE + i], n);
    }
}

// ---------------- prep: weight-norm W_out (rows of 64), warp/row ----------------
__global__ __launch_bounds__(256) void k_prep_wout(const float* __restrict__ v_out,
                                                   const float* __restrict__ g_out)
{
    int gw = (blockIdx.x * 256 + threadIdx.x) >> 5;
    int l = threadIdx.x & 31;
    float a = v_out[gw * CC + l], b = v_out[gw * CC + l + 32];
    float s = a * a + b * b;
#pragma unroll
    for (int off = 16; off; off >>= 1) s += __shfl_xor_sync(0xffffffffu, s, off);
    float n = __fsqrt_rn(s), g = g_out[gw];
    g_Wout[gw * CC + l]      = __fdiv_rn(g * a, n);
    g_Wout[gw * CC + l + 32] = __fdiv_rn(g * b, n);
}

// ---------------- prep: normalize codebook -> (-2x) transposed + ||.||^2 ----------------
__global__ __launch_bounds__(256) void k_prep_cb(const float* __restrict__ cb)
{
    int k = (blockIdx.x * 256 + threadIdx.x) >> 5;
    int l = threadIdx.x & 31;
    float a = cb[k * CC + l], b = cb[k * CC + l + 32];
    float s = a * a + b * b;
#pragma unroll
    for (int off = 16; off; off >>= 1) s += __shfl_xor_sync(0xffffffffu, s, off);
    float n = fmaxf(__fsqrt_rn(s), 1e-12f);
    float ca = __fdiv_rn(a, n), cbv = __fdiv_rn(b, n);
    g_cbT[l * Kk + k]        = -2.f * ca;
    g_cbT[(l + 32) * Kk + k] = -2.f * cbv;
    float s2 = ca * ca + cbv * cbv;
#pragma unroll
    for (int off = 16; off; off >>= 1) s2 += __shfl_xor_sync(0xffffffffu, s2, off);
    if (l == 0) g_cbn2[k] = s2;
}

// ---------------- gemm: Out[64 x 128t] = W[64 x K] @ X[K x 128t] ----------------
// block = 64 o x 128 t; thread tile 4o x 8t (two strided float4 t-groups).
// Register-level software pipeline: next-k operands prefetched during current-k FMAs.
template<bool XALN16>
__global__ __launch_bounds__(256, 2) void k_gemm64(const float* __restrict__ W, int K, long long WzS,
                                                   const float* __restrict__ X, long long XyS,
                                                   float* __restrict__ O, long long OyS, long long OzS)
{
    __shared__ __align__(16) float Ws[32][68];
    __shared__ __align__(16) float Xs[32][128];
    const float* Wp = W + (long long)blockIdx.z * WzS;
    const float* Xp = X + (long long)blockIdx.y * XyS;
    float* Op = O + (long long)blockIdx.y * OyS + (long long)blockIdx.z * OzS + (long long)blockIdx.x * 128;
    int tid = threadIdx.x;
    int to = tid >> 4, tt = tid & 15;
    long long t0 = (long long)blockIdx.x * 128;

    u64 acc[4][4];
#pragma unroll
    for (int i = 0; i < 4; i++)
#pragma unroll
        for (int j = 0; j < 4; j++) acc[i][j] = 0ull;

    for (int kc = 0; kc < K; kc += 32) {
#pragma unroll
        for (int it = 0; it < 2; it++) {
            int rr = tid + it * 256;                 // 512 quads: 64 o x 8 kq
            int o = rr >> 3, kq = rr & 7;
            float4 w = *(const float4*)&Wp[(long long)o * K + kc + kq * 4];
            Ws[kq * 4 + 0][o] = w.x; Ws[kq * 4 + 1][o] = w.y;
            Ws[kq * 4 + 2][o] = w.z; Ws[kq * 4 + 3][o] = w.w;
        }
#pragma unroll
        for (int it = 0; it < 4; it++) {
            int rr = tid + it * 256;                 // 1024 quads: 32 k x 32 t4
            int i = rr >> 5, t4 = rr & 31;
            long long gidx = (long long)(kc + i) * Tt + t0 + t4 * 4;
            if (XALN16) {
                *(float4*)&Xs[i][t4 * 4] = *(const float4*)&Xp[gidx];
            } else {
                const u64* p = (const u64*)&Xp[gidx];
                *(u64*)&Xs[i][t4 * 4]     = p[0];
                *(u64*)&Xs[i][t4 * 4 + 2] = p[1];
            }
        }
        __syncthreads();
        // register pipeline across k
        float4 wn  = *(const float4*)&Ws[0][to * 4];
        float4 xan = *(const float4*)&Xs[0][tt * 4];
        float4 xbn = *(const float4*)&Xs[0][64 + tt * 4];
#pragma unroll 8
        for (int k = 0; k < 32; k++) {
            float4 w = wn, xa = xan, xb = xbn;
            if (k < 31) {
                wn  = *(const float4*)&Ws[k + 1][to * 4];
                xan = *(const float4*)&Xs[k + 1][tt * 4];
                xbn = *(const float4*)&Xs[k + 1][64 + tt * 4];
            }
            u64 xa0 = pk2(xa.x, xa.y), xa1 = pk2(xa.z, xa.w);
            u64 xb0 = pk2(xb.x, xb.y), xb1 = pk2(xb.z, xb.w);
            u64 w0 = pk2(w.x, w.x), w1 = pk2(w.y, w.y), w2 = pk2(w.z, w.z), w3 = pk2(w.w, w.w);
            fma2(acc[0][0], w0, xa0); fma2(acc[0][1], w0, xa1); fma2(acc[0][2], w0, xb0); fma2(acc[0][3], w0, xb1);
            fma2(acc[1][0], w1, xa0); fma2(acc[1][1], w1, xa1); fma2(acc[1][2], w1, xb0); fma2(acc[1][3], w1, xb1);
            fma2(acc[2][0], w2, xa0); fma2(acc[2][1], w2, xa1); fma2(acc[2][2], w2, xb0); fma2(acc[2][3], w2, xb1);
            fma2(acc[3][0], w3, xa0); fma2(acc[3][1], w3, xa1); fma2(acc[3][2], w3, xb0); fma2(acc[3][3], w3, xb1);
        }
        __syncthreads();
    }
#pragma unroll
    for (int oj = 0; oj < 4; oj++) {
        long long rb = (long long)(to * 4 + oj) * Tt;
        *(u64*)&Op[rb + tt * 4]          = acc[oj][0];
        *(u64*)&Op[rb + tt * 4 + 2]      = acc[oj][1];
        *(u64*)&Op[rb + 64 + tt * 4]     = acc[oj][2];
        *(u64*)&Op[rb + 64 + tt * 4 + 2] = acc[oj][3];
    }
}

// ---------------- dist: big-tile, low-wavefront, smem + register pipelined ----------------
// block = 128 t, 256 threads; 32 chunks of 128 k; thread tile 8t x 8k.
// E plain smem 2-way-broadcast; C lane-consecutive; cbT pre-scaled by -2 and
// acc initialized from ||cb_n||^2 -> accumulator IS the score.
static constexpr int ETS = 132;
static constexpr int CTS = 132;
static constexpr int CSTG = 64 * CTS;
static constexpr int SMEM_DIST = (64 * ETS + 2 * CSTG + 2 * 128 + 128 + 128) * 4;  // 103424 B

__global__ __launch_bounds__(256, 2) void k_dist(const float* __restrict__ cb,
                                                 float* __restrict__ out)
{
    extern __shared__ float sm[];
    float* Es    = sm;                           // [64 o][132]
    float* CsB   = sm + 64 * ETS;                // [2][64 o][132]
    float* cb2   = sm + 64 * ETS + 2 * CSTG;     // [2][128]
    float* den   = cb2 + 256;                    // [128]
    int*   scode = (int*)(den + 128);            // [128]
    float* redv  = CsB;                          // overlap after chunk loop
    int*   redi  = (int*)(CsB + 2048);

    int b = blockIdx.y, tid = threadIdx.x;
    long long t0 = (long long)blockIdx.x * 128;
    int tx = tid & 15;           // k-octet slot
    int ty = tid >> 4;           // t-group of 8
    const long long xbase = O_XPROJ + (long long)b * (CC * Tt) + t0;

    // load x_proj tile (8B-aligned region): 64 o x 128 t
#pragma unroll
    for (int it = 0; it < 16; it++) {
        int rr = tid + it * 256;                 // 4096 u64: 64 o x 64 t2
        int o = rr >> 6, t2 = rr & 63;
        *(u64*)&Es[o * ETS + t2 * 2] = *(const u64*)&out[xbase + (long long)o * Tt + t2 * 2];
    }
    __syncthreads();
    if (tid < 128) {
        float s = 0.f;
#pragma unroll 8
        for (int o = 0; o < 64; o++) { float v = Es[o * ETS + tid]; s += v * v; }
        den[tid] = fmaxf(__fsqrt_rn(s), 1e-12f);
    }
    __syncthreads();
#pragma unroll
    for (int it = 0; it < 16; it++) {
        int rr = tid + it * 256;
        int o = rr >> 6, t2 = rr & 63;
        float2 v = upk2(*(const u64*)&Es[o * ETS + t2 * 2]);
        v.x = __fdiv_rn(v.x, den[t2 * 2]);
        v.y = __fdiv_rn(v.y, den[t2 * 2 + 1]);
        *(u64*)&Es[o * ETS + t2 * 2] = pk2(v.x, v.y);
    }

    auto loadc = [&](int st, int kc0) {
        float* Cs = CsB + st * CSTG;
#pragma unroll
        for (int it = 0; it < 8; it++) {
            int rr = tid + it * 256;             // 2048 quads: 64 o x 32 k4
            int o = rr >> 5, k4 = rr & 31;
            cp16(s2u(&Cs[o * CTS + k4 * 4]), &g_cbT[o * Kk + kc0 + k4 * 4]);
        }
        if (tid < 32) cp16(s2u(&cb2[st * 128 + tid * 4]), &g_cbn2[kc0 + tid * 4]);
    };

    float bval[8]; int bidx[8];
#pragma unroll
    for (int i = 0; i < 8; i++) { bval[i] = 3.4028235e38f; bidx[i] = 0; }

    loadc(0, 0); cpcommit();
    for (int ch = 0; ch < 32; ch++) {
        if (ch + 1 < 32) loadc((ch + 1) & 1, (ch + 1) * 128);
        cpcommit();
        cpwait1();
        __syncthreads();
        const float* Cs = CsB + (ch & 1) * CSTG;
        const float* cbn2s = cb2 + (ch & 1) * 128;
        int kc0 = ch * 128;

        const u64* ip = (const u64*)&cbn2s[tx * 8];
        u64 i0 = ip[0], i1 = ip[1], i2 = ip[2], i3 = ip[3];
        u64 acc[8][4];
#pragma unroll
        for (int tl = 0; tl < 8; tl++) {
            acc[tl][0] = i0; acc[tl][1] = i1; acc[tl][2] = i2; acc[tl][3] = i3;
        }

        // register pipeline across o: prefetch next C-quad and first E-half
        const u64* cp0 = (const u64*)&Cs[tx * 8];
        u64 cn0 = cp0[0], cn1 = cp0[1], cn2 = cp0[2], cn3 = cp0[3];
        float4 ean = *(const float4*)&Es[ty * 8];
#pragma unroll 4
        for (int o = 0; o < 64; o++) {
            u64 c0 = cn0, c1 = cn1, c2 = cn2, c3 = cn3;
            float4 ea = ean;
            float4 eb = *(const float4*)&Es[o * ETS + ty * 8 + 4];   // 2nd half, used late
            if (o < 63) {
                const u64* cpn = (const u64*)&Cs[(o + 1) * CTS + tx * 8];
                cn0 = cpn[0]; cn1 = cpn[1]; cn2 = cpn[2]; cn3 = cpn[3];
                ean = *(const float4*)&Es[(o + 1) * ETS + ty * 8];
            }
            u64 e0 = pk2(ea.x, ea.x), e1 = pk2(ea.y, ea.y), e2 = pk2(ea.z, ea.z), e3 = pk2(ea.w, ea.w);
            fma2(acc[0][0], e0, c0); fma2(acc[0][1], e0, c1); fma2(acc[0][2], e0, c2); fma2(acc[0][3], e0, c3);
            fma2(acc[1][0], e1, c0); fma2(acc[1][1], e1, c1); fma2(acc[1][2], e1, c2); fma2(acc[1][3], e1, c3);
            fma2(acc[2][0], e2, c0); fma2(acc[2][1], e2, c1); fma2(acc[2][2], e2, c2); fma2(acc[2][3], e2, c3);
            fma2(acc[3][0], e3, c0); fma2(acc[3][1], e3, c1); fma2(acc[3][2], e3, c2); fma2(acc[3][3], e3, c3);
            u64 e4 = pk2(eb.x, eb.x), e5 = pk2(eb.y, eb.y), e6 = pk2(eb.z, eb.z), e7 = pk2(eb.w, eb.w);
            fma2(acc[4][0], e4, c0); fma2(acc[4][1], e4, c1); fma2(acc[4][2], e4, c2); fma2(acc[4][3], e4, c3);
            fma2(acc[5][0], e5, c0); fma2(acc[5][1], e5, c1); fma2(acc[5][2], e5, c2); fma2(acc[5][3], e5, c3);
            fma2(acc[6][0], e6, c0); fma2(acc[6][1], e6, c1); fma2(acc[6][2], e6, c2); fma2(acc[6][3], e6, c3);
            fma2(acc[7][0], e7, c0); fma2(acc[7][1], e7, c1); fma2(acc[7][2], e7, c2); fma2(acc[7][3], e7, c3);
        }
        // ascending k within thread; strict < keeps first min (matches jnp.argmin)
#pragma unroll
        for (int tl = 0; tl < 8; tl++) {
#pragma unroll
            for (int j = 0; j < 4; j++) {
                float2 d = upk2(acc[tl][j]);
                int kg = kc0 + tx * 8 + j * 2;
                if (d.x < bval[tl]) { bval[tl] = d.x; bidx[tl] = kg; }
                if (d.y < bval[tl]) { bval[tl] = d.y; bidx[tl] = kg + 1; }
            }
        }
        __syncthreads();
    }
    // cross-thread argmin reduction over the 16 k-slots per t
#pragma unroll
    for (int tl = 0; tl < 8; tl++) {
        redv[(ty * 8 + tl) * 16 + tx] = bval[tl];
        redi[(ty * 8 + tl) * 16 + tx] = bidx[tl];
    }
    __syncthreads();
    if (tid < 128) {
        float bv = 3.4028235e38f; int bi = 0x7fffffff;
#pragma unroll
        for (int j = 0; j < 16; j++) {
            float v = redv[tid * 16 + j]; int i = redi[tid * 16 + j];
            if (v < bv || (v == bv && i < bi)) { bv = v; bi = i; }
        }
        scode[tid] = bi;
        out[O_CODES + (long long)b * Tt + t0 + tid] = (float)bi;
    }
    __syncthreads();

    // gather q, write quantized_proj = xp + (q - xp), accumulate loss
    {
        int t = tid & 127, og = tid >> 7;        // og 0..1 -> 32 o each
        int code = scode[t];
        const float* cbrow = cb + (long long)code * CC + og * 32;
        long long xb2 = O_XPROJ + (long long)b * (CC * Tt) + t0 + t;
        long long qb2 = O_QPROJ + (long long)b * (CC * Tt) + t0 + t;
        float ls = 0.f;
#pragma unroll
        for (int j = 0; j < 32; j++) {
            long long ro = (long long)(og * 32 + j) * Tt;
            float xp = out[xb2 + ro];
            float q  = cbrow[j];
            float d  = q - xp;
            out[qb2 + ro] = xp + d;
            ls += d * d;
        }
        __syncthreads();
        redv[tid] = ls; __syncthreads();
        for (int off = 128; off > 0; off >>= 1) {
            if (tid < off) redv[tid] += redv[tid + off];
            __syncthreads();
        }
        if (tid == 0) g_lpart[blockIdx.y * gridDim.x + blockIdx.x] = (double)redv[0];
    }
}

// ---------------- final loss reduction (256 partials) ----------------
__global__ __launch_bounds__(256) void k_loss(float* __restrict__ out)
{
    __shared__ double sb[256];
    int tid = threadIdx.x;
    sb[tid] = g_lpart[tid];
    __syncthreads();
    for (int off = 128; off > 0; off >>= 1) {
        if (tid < off) sb[tid] += sb[tid + off];
        __syncthreads();
    }
    if (tid == 0) {
        float l = (float)(sb[0] / (double)(16.0 * 64.0 * 2048.0));
        out[O_CBL] = l;
        out[O_CML] = l;
    }
}

extern "C" void kernel_launch(void* const* d_in, const int* in_sizes, int n_in,
                              void* d_out, int out_size) {
    (void)in_sizes; (void)n_in; (void)out_size;
    const float* x    = (const float*)d_in[0];
    const float* v_in = (const float*)d_in[1];
    const float* g_in = (const float*)d_in[2];
    const float* v_out= (const float*)d_in[3];
    const float* g_out= (const float*)d_in[4];
    const float* cb   = (const float*)d_in[5];
    float* out = (float*)d_out;

    cudaFuncSetAttribute(k_dist, cudaFuncAttributeMaxDynamicSharedMemorySize, SMEM_DIST);

    k_prep_win<<<64, 256>>>(v_in, g_in);
    k_prep_wout<<<128, 256>>>(v_out, g_out);
    k_prep_cb<<<512, 256>>>(cb);

    float* winp; cudaGetSymbolAddress((void**)&winp, g_Win);
    float* woutp; cudaGetSymbolAddress((void**)&woutp, g_Wout);

    // x_proj = W_in @ x : per-b 64x2048, K=1024
    k_gemm64<true><<<dim3(16, 16, 1), 256>>>(winp, CE, 0ll,
                                             x, (long long)CE * Tt,
                                             out + O_XPROJ, (long long)CC * Tt, 0ll);

    // codes / qproj / loss partials : 16 t-tiles x 16 b
    k_dist<<<dim3(16, 16), 256, SMEM_DIST>>>(cb, out);
    k_loss<<<1, 256>>>(out);

    // quantized = W_out @ quantized_proj : per-(b, o-block) 64x2048, K=64
    k_gemm64<false><<<dim3(16, 16, 16), 256>>>(woutp, CC, (long long)64 * CC,
                                               out + O_QPROJ, (long long)CC * Tt,
                                               out + O_QUANT, (long long)CE * Tt, (long long)64 * Tt);
}

// round 12
// speedup vs baseline: 1.0563x; 1.0563x over previous
#include <cuda_runtime.h>

typedef unsigned long long u64;

static constexpr int Bb = 16;
static constexpr int CE = 1024;
static constexpr int Tt = 2048;
static constexpr int CC = 64;
static constexpr int Kk = 4096;

static constexpr long long O_CODES = 0;
static constexpr long long O_QUANT = 32768;
static constexpr long long N_QUANT = (long long)Bb * CE * Tt;    // 33554432
static constexpr long long O_CBL   = O_QUANT + N_QUANT;           // 33587200
static constexpr long long O_CML   = O_CBL + 1;
static constexpr long long O_XPROJ = O_CML + 1;                   // 33587202 (even -> 8B aligned)
static constexpr long long N_XP    = (long long)Bb * CC * Tt;     // 2097152
static constexpr long long O_QPROJ = O_XPROJ + N_XP;              // 35684354 (even)

// scratch (static device globals; no runtime allocation)
__device__ __align__(16) float  g_Win[CC * CE];
__device__ __align__(16) float  g_Wout[CE * CC];
__device__ __align__(16) float  g_cbT[CC * Kk];    // (-2 * normalized codebook), [o][k]
__device__ __align__(16) float  g_cbn2[Kk];        // ||cb_n||^2
__device__ __align__(16) float  g_WC[Kk * CE];     // WC[k][o] = sum_i cb[k,i] * W_out[o,i]  (16.8 MB)
__device__ double g_lpart[256];

__device__ __forceinline__ u64 pk2(float lo, float hi) {
    u64 r; asm("mov.b64 %0, {%1, %2};" : "=l"(r) : "f"(lo), "f"(hi)); return r;
}
__device__ __forceinline__ float2 upk2(u64 v) {
    float2 r; asm("mov.b64 {%0, %1}, %2;" : "=f"(r.x), "=f"(r.y) : "l"(v)); return r;
}
__device__ __forceinline__ void fma2(u64 &d, u64 a, u64 b) {
    asm("fma.rn.f32x2 %0, %1, %2, %0;" : "+l"(d) : "l"(a), "l"(b));
}
__device__ __forceinline__ unsigned s2u(const void* p) {
    return (unsigned)__cvta_generic_to_shared(p);
}
__device__ __forceinline__ void cp16(unsigned s, const void* g) {
    asm volatile("cp.async.cg.shared.global [%0], [%1], 16;" :: "r"(s), "l"(g));
}
__device__ __forceinline__ void cpcommit() { asm volatile("cp.async.commit_group;"); }
__device__ __forceinline__ void cpwait1()  { asm volatile("cp.async.wait_group 1;"); }

// ---------------- prep: weight-norm W_in (rows of 1024) ----------------
__global__ __launch_bounds__(256) void k_prep_win(const float* __restrict__ v_in,
                                                  const float* __restrict__ g_in)
{
    __shared__ float sb[256];
    __shared__ float snorm;
    int o = blockIdx.x, tid = threadIdx.x;
    float s = 0.f;
#pragma unroll
    for (int j = 0; j < 4; j++) { float v = v_in[o * CE + tid + j * 256]; s += v * v; }
    sb[tid] = s; __syncthreads();
    for (int off = 128; off > 0; off >>= 1) { if (tid < off) sb[tid] += sb[tid + off]; __syncthreads(); }
    if (tid == 0) snorm = __fsqrt_rn(sb[0]);
    __syncthreads();
    float n = snorm, g = g_in[o];
#pragma unroll
    for (int j = 0; j < 4; j++) {
        int i = tid + j * 256;
        g_Win[o * CE + i] = __fdiv_rn(g * v_in[o * CE + i], n);
    }
}

// ---------------- prep: weight-norm W_out (rows of 64), warp/row ----------------
__global__ __launch_bounds__(256) void k_prep_wout(const float* __restrict__ v_out,
                                                   const float* __restrict__ g_out)
{
    int gw = (blockIdx.x * 256 + threadIdx.x) >> 5;
    int l = threadIdx.x & 31;
    float a = v_out[gw * CC + l], b = v_out[gw * CC + l + 32];
    float s = a * a + b * b;
#pragma unroll
    for (int off = 16; off; off >>= 1) s += __shfl_xor_sync(0xffffffffu, s, off);
    float n = __fsqrt_rn(s), g = g_out[gw];
    g_Wout[gw * CC + l]      = __fdiv_rn(g * a, n);
    g_Wout[gw * CC + l + 32] = __fdiv_rn(g * b, n);
}

// ---------------- prep: normalize codebook -> (-2x) transposed + ||.||^2 ----------------
__global__ __launch_bounds__(256) void k_prep_cb(const float* __restrict__ cb)
{
    int k = (blockIdx.x * 256 + threadIdx.x) >> 5;
    int l = threadIdx.x & 31;
    float a = cb[k * CC + l], b = cb[k * CC + l + 32];
    float s = a * a + b * b;
#pragma unroll
    for (int off = 16; off; off >>= 1) s += __shfl_xor_sync(0xffffffffu, s, off);
    float n = fmaxf(__fsqrt_rn(s), 1e-12f);
    float ca = __fdiv_rn(a, n), cbv = __fdiv_rn(b, n);
    g_cbT[l * Kk + k]        = -2.f * ca;
    g_cbT[(l + 32) * Kk + k] = -2.f * cbv;
    float s2 = ca * ca + cbv * cbv;
#pragma unroll
    for (int off = 16; off; off >>= 1) s2 += __shfl_xor_sync(0xffffffffu, s2, off);
    if (l == 0) g_cbn2[k] = s2;
}

// ---------------- WC = codebook @ W_out^T : WC[k][o], 4096 x 1024, K=64 ----------------
// block = 64 codes x 128 o, 256 threads, thread 4 codes x 8 o (gemm64-style).
__global__ __launch_bounds__(256) void k_wc(const float* __restrict__ cb)
{
    __shared__ __align__(16) float CBt[64][68];    // [i][code]
    __shared__ __align__(16) float WT[64][132];    // [i][o]
    int k0 = blockIdx.x * 64;
    int o0 = blockIdx.y * 128;
    int tid = threadIdx.x;
    int to = tid >> 4, tt = tid & 15;

    // stage codebook tile transposed: CBt[i][code]
#pragma unroll
    for (int it = 0; it < 4; it++) {
        int rr = tid + it * 256;                   // 1024 quads: 64 codes x 16 iq
        int code = rr >> 4, q = rr & 15;
        float4 v = *(const float4*)&cb[(long long)(k0 + code) * CC + q * 4];
        CBt[q * 4 + 0][code] = v.x; CBt[q * 4 + 1][code] = v.y;
        CBt[q * 4 + 2][code] = v.z; CBt[q * 4 + 3][code] = v.w;
    }
    // stage W_out tile transposed: WT[i][o]
#pragma unroll
    for (int it = 0; it < 8; it++) {
        int rr = tid + it * 256;                   // 2048 quads: 128 o x 16 iq
        int o = rr >> 4, q = rr & 15;
        float4 v = *(const float4*)&g_Wout[(long long)(o0 + o) * CC + q * 4];
        WT[q * 4 + 0][o] = v.x; WT[q * 4 + 1][o] = v.y;
        WT[q * 4 + 2][o] = v.z; WT[q * 4 + 3][o] = v.w;
    }
    __syncthreads();

    u64 acc[4][4];
#pragma unroll
    for (int i = 0; i < 4; i++)
#pragma unroll
        for (int j = 0; j < 4; j++) acc[i][j] = 0ull;

#pragma unroll 8
    for (int i = 0; i < 64; i++) {
        float4 w  = *(const float4*)&CBt[i][to * 4];
        float4 xa = *(const float4*)&WT[i][tt * 4];
        float4 xb = *(const float4*)&WT[i][64 + tt * 4];
        u64 xa0 = pk2(xa.x, xa.y), xa1 = pk2(xa.z, xa.w);
        u64 xb0 = pk2(xb.x, xb.y), xb1 = pk2(xb.z, xb.w);
        u64 w0 = pk2(w.x, w.x), w1 = pk2(w.y, w.y), w2 = pk2(w.z, w.z), w3 = pk2(w.w, w.w);
        fma2(acc[0][0], w0, xa0); fma2(acc[0][1], w0, xa1); fma2(acc[0][2], w0, xb0); fma2(acc[0][3], w0, xb1);
        fma2(acc[1][0], w1, xa0); fma2(acc[1][1], w1, xa1); fma2(acc[1][2], w1, xb0); fma2(acc[1][3], w1, xb1);
        fma2(acc[2][0], w2, xa0); fma2(acc[2][1], w2, xa1); fma2(acc[2][2], w2, xb0); fma2(acc[2][3], w2, xb1);
        fma2(acc[3][0], w3, xa0); fma2(acc[3][1], w3, xa1); fma2(acc[3][2], w3, xb0); fma2(acc[3][3], w3, xb1);
    }
#pragma unroll
    for (int oj = 0; oj < 4; oj++) {
        float* row = &g_WC[(long long)(k0 + to * 4 + oj) * CE + o0];
        *(u64*)&row[tt * 4]          = acc[oj][0];
        *(u64*)&row[tt * 4 + 2]      = acc[oj][1];
        *(u64*)&row[64 + tt * 4]     = acc[oj][2];
        *(u64*)&row[64 + tt * 4 + 2] = acc[oj][3];
    }
}

// ---------------- gather: quantized[b,o,t] = WC[code[b,t]][o] ----------------
// block = (b, 128-t tile); smem-transposed so WC reads AND out writes are coalesced.
__global__ __launch_bounds__(256) void k_gather(float* __restrict__ out)
{
    __shared__ __align__(16) float Tile[64 * 132];
    __shared__ int scode[128];
    int b = blockIdx.y, tid = threadIdx.x;
    long long t0 = (long long)blockIdx.x * 128;

    if (tid < 128) scode[tid] = (int)out[O_CODES + (long long)b * Tt + t0 + tid];
    __syncthreads();

    for (int oc = 0; oc < 16; oc++) {
        // load 64 o x 128 t from WC (rows contiguous in o)
#pragma unroll
        for (int it = 0; it < 8; it++) {
            int rr = tid + it * 256;               // 2048 quads: 128 t x 16 oq
            int t = rr >> 4, q = rr & 15;
            float4 v = *(const float4*)&g_WC[(long long)scode[t] * CE + oc * 64 + q * 4];
            Tile[(q * 4 + 0) * 132 + t] = v.x;
            Tile[(q * 4 + 1) * 132 + t] = v.y;
            Tile[(q * 4 + 2) * 132 + t] = v.z;
            Tile[(q * 4 + 3) * 132 + t] = v.w;
        }
        __syncthreads();
        // write coalesced over t
#pragma unroll
        for (int it = 0; it < 8; it++) {
            int rr = tid + it * 256;               // 2048 quads: 64 o x 32 t4
            int o = rr >> 5, t4 = rr & 31;
            *(float4*)&out[O_QUANT + (long long)b * CE * Tt + (long long)(oc * 64 + o) * Tt + t0 + t4 * 4]
                = *(const float4*)&Tile[o * 132 + t4 * 4];
        }
        __syncthreads();
    }
}

// ---------------- gemm: Out[64 x 128t] = W[64 x K] @ X[K x 128t] ----------------
// block = 64 o x 128 t; thread tile 4o x 8t; register pipeline across k.
template<bool XALN16>
__global__ __launch_bounds__(256, 2) void k_gemm64(const float* __restrict__ W, int K, long long WzS,
                                                   const float* __restrict__ X, long long XyS,
                                                   float* __restrict__ O, long long OyS, long long OzS)
{
    __shared__ __align__(16) float Ws[32][68];
    __shared__ __align__(16) float Xs[32][128];
    const float* Wp = W + (long long)blockIdx.z * WzS;
    const float* Xp = X + (long long)blockIdx.y * XyS;
    float* Op = O + (long long)blockIdx.y * OyS + (long long)blockIdx.z * OzS + (long long)blockIdx.x * 128;
    int tid = threadIdx.x;
    int to = tid >> 4, tt = tid & 15;
    long long t0 = (long long)blockIdx.x * 128;

    u64 acc[4][4];
#pragma unroll
    for (int i = 0; i < 4; i++)
#pragma unroll
        for (int j = 0; j < 4; j++) acc[i][j] = 0ull;

    for (int kc = 0; kc < K; kc += 32) {
#pragma unroll
        for (int it = 0; it < 2; it++) {
            int rr = tid + it * 256;
            int o = rr >> 3, kq = rr & 7;
            float4 w = *(const float4*)&Wp[(long long)o * K + kc + kq * 4];
            Ws[kq * 4 + 0][o] = w.x; Ws[kq * 4 + 1][o] = w.y;
            Ws[kq * 4 + 2][o] = w.z; Ws[kq * 4 + 3][o] = w.w;
        }
#pragma unroll
        for (int it = 0; it < 4; it++) {
            int rr = tid + it * 256;
            int i = rr >> 5, t4 = rr & 31;
            long long gidx = (long long)(kc + i) * Tt + t0 + t4 * 4;
            if (XALN16) {
                *(float4*)&Xs[i][t4 * 4] = *(const float4*)&Xp[gidx];
            } else {
                const u64* p = (const u64*)&Xp[gidx];
                *(u64*)&Xs[i][t4 * 4]     = p[0];
                *(u64*)&Xs[i][t4 * 4 + 2] = p[1];
            }
        }
        __syncthreads();
        float4 wn  = *(const float4*)&Ws[0][to * 4];
        float4 xan = *(const float4*)&Xs[0][tt * 4];
        float4 xbn = *(const float4*)&Xs[0][64 + tt * 4];
#pragma unroll 8
        for (int k = 0; k < 32; k++) {
            float4 w = wn, xa = xan, xb = xbn;
            if (k < 31) {
                wn  = *(const float4*)&Ws[k + 1][to * 4];
                xan = *(const float4*)&Xs[k + 1][tt * 4];
                xbn = *(const float4*)&Xs[k + 1][64 + tt * 4];
            }
            u64 xa0 = pk2(xa.x, xa.y), xa1 = pk2(xa.z, xa.w);
            u64 xb0 = pk2(xb.x, xb.y), xb1 = pk2(xb.z, xb.w);
            u64 w0 = pk2(w.x, w.x), w1 = pk2(w.y, w.y), w2 = pk2(w.z, w.z), w3 = pk2(w.w, w.w);
            fma2(acc[0][0], w0, xa0); fma2(acc[0][1], w0, xa1); fma2(acc[0][2], w0, xb0); fma2(acc[0][3], w0, xb1);
            fma2(acc[1][0], w1, xa0); fma2(acc[1][1], w1, xa1); fma2(acc[1][2], w1, xb0); fma2(acc[1][3], w1, xb1);
            fma2(acc[2][0], w2, xa0); fma2(acc[2][1], w2, xa1); fma2(acc[2][2], w2, xb0); fma2(acc[2][3], w2, xb1);
            fma2(acc[3][0], w3, xa0); fma2(acc[3][1], w3, xa1); fma2(acc[3][2], w3, xb0); fma2(acc[3][3], w3, xb1);
        }
        __syncthreads();
    }
#pragma unroll
    for (int oj = 0; oj < 4; oj++) {
        long long rb = (long long)(to * 4 + oj) * Tt;
        *(u64*)&Op[rb + tt * 4]          = acc[oj][0];
        *(u64*)&Op[rb + tt * 4 + 2]      = acc[oj][1];
        *(u64*)&Op[rb + 64 + tt * 4]     = acc[oj][2];
        *(u64*)&Op[rb + 64 + tt * 4 + 2] = acc[oj][3];
    }
}

// ---------------- dist: R9-proven big-tile pipelined version ----------------
static constexpr int ETS = 132;
static constexpr int CTS = 132;
static constexpr int CSTG = 64 * CTS;
static constexpr int SMEM_DIST = (64 * ETS + 2 * CSTG + 2 * 128 + 128 + 128) * 4;  // 103424 B

__global__ __launch_bounds__(256) void k_dist(const float* __restrict__ cb,
                                              float* __restrict__ out)
{
    extern __shared__ float sm[];
    float* Es    = sm;                           // [64 o][132]
    float* CsB   = sm + 64 * ETS;                // [2][64 o][132]
    float* cb2   = sm + 64 * ETS + 2 * CSTG;     // [2][128]
    float* den   = cb2 + 256;                    // [128]
    int*   scode = (int*)(den + 128);            // [128]
    float* redv  = CsB;                          // overlap after chunk loop
    int*   redi  = (int*)(CsB + 2048);

    int b = blockIdx.y, tid = threadIdx.x;
    long long t0 = (long long)blockIdx.x * 128;
    int tx = tid & 15;           // k-octet slot
    int ty = tid >> 4;           // t-group of 8
    const long long xbase = O_XPROJ + (long long)b * (CC * Tt) + t0;

#pragma unroll
    for (int it = 0; it < 16; it++) {
        int rr = tid + it * 256;
        int o = rr >> 6, t2 = rr & 63;
        *(u64*)&Es[o * ETS + t2 * 2] = *(const u64*)&out[xbase + (long long)o * Tt + t2 * 2];
    }
    __syncthreads();
    if (tid < 128) {
        float s = 0.f;
#pragma unroll 8
        for (int o = 0; o < 64; o++) { float v = Es[o * ETS + tid]; s += v * v; }
        den[tid] = fmaxf(__fsqrt_rn(s), 1e-12f);
    }
    __syncthreads();
#pragma unroll
    for (int it = 0; it < 16; it++) {
        int rr = tid + it * 256;
        int o = rr >> 6, t2 = rr & 63;
        float2 v = upk2(*(const u64*)&Es[o * ETS + t2 * 2]);
        v.x = __fdiv_rn(v.x, den[t2 * 2]);
        v.y = __fdiv_rn(v.y, den[t2 * 2 + 1]);
        *(u64*)&Es[o * ETS + t2 * 2] = pk2(v.x, v.y);
    }

    auto loadc = [&](int st, int kc0) {
        float* Cs = CsB + st * CSTG;
#pragma unroll
        for (int it = 0; it < 8; it++) {
            int rr = tid + it * 256;
            int o = rr >> 5, k4 = rr & 31;
            cp16(s2u(&Cs[o * CTS + k4 * 4]), &g_cbT[o * Kk + kc0 + k4 * 4]);
        }
        if (tid < 32) cp16(s2u(&cb2[st * 128 + tid * 4]), &g_cbn2[kc0 + tid * 4]);
    };

    float bval[8]; int bidx[8];
#pragma unroll
    for (int i = 0; i < 8; i++) { bval[i] = 3.4028235e38f; bidx[i] = 0; }

    loadc(0, 0); cpcommit();
    for (int ch = 0; ch < 32; ch++) {
        if (ch + 1 < 32) loadc((ch + 1) & 1, (ch + 1) * 128);
        cpcommit();
        cpwait1();
        __syncthreads();
        const float* Cs = CsB + (ch & 1) * CSTG;
        const float* cbn2s = cb2 + (ch & 1) * 128;
        int kc0 = ch * 128;

        const u64* ip = (const u64*)&cbn2s[tx * 8];
        u64 i0 = ip[0], i1 = ip[1], i2 = ip[2], i3 = ip[3];
        u64 acc[8][4];
#pragma unroll
        for (int tl = 0; tl < 8; tl++) {
            acc[tl][0] = i0; acc[tl][1] = i1; acc[tl][2] = i2; acc[tl][3] = i3;
        }

#pragma unroll 4
        for (int o = 0; o < 64; o++) {
            const u64* cp = (const u64*)&Cs[o * CTS + tx * 8];
            u64 c0 = cp[0], c1 = cp[1], c2 = cp[2], c3 = cp[3];
            float4 ea = *(const float4*)&Es[o * ETS + ty * 8];
            float4 eb = *(const float4*)&Es[o * ETS + ty * 8 + 4];
            u64 e0 = pk2(ea.x, ea.x), e1 = pk2(ea.y, ea.y), e2 = pk2(ea.z, ea.z), e3 = pk2(ea.w, ea.w);
            u64 e4 = pk2(eb.x, eb.x), e5 = pk2(eb.y, eb.y), e6 = pk2(eb.z, eb.z), e7 = pk2(eb.w, eb.w);
            fma2(acc[0][0], e0, c0); fma2(acc[0][1], e0, c1); fma2(acc[0][2], e0, c2); fma2(acc[0][3], e0, c3);
            fma2(acc[1][0], e1, c0); fma2(acc[1][1], e1, c1); fma2(acc[1][2], e1, c2); fma2(acc[1][3], e1, c3);
            fma2(acc[2][0], e2, c0); fma2(acc[2][1], e2, c1); fma2(acc[2][2], e2, c2); fma2(acc[2][3], e2, c3);
            fma2(acc[3][0], e3, c0); fma2(acc[3][1], e3, c1); fma2(acc[3][2], e3, c2); fma2(acc[3][3], e3, c3);
            fma2(acc[4][0], e4, c0); fma2(acc[4][1], e4, c1); fma2(acc[4][2], e4, c2); fma2(acc[4][3], e4, c3);
            fma2(acc[5][0], e5, c0); fma2(acc[5][1], e5, c1); fma2(acc[5][2], e5, c2); fma2(acc[5][3], e5, c3);
            fma2(acc[6][0], e6, c0); fma2(acc[6][1], e6, c1); fma2(acc[6][2], e6, c2); fma2(acc[6][3], e6, c3);
            fma2(acc[7][0], e7, c0); fma2(acc[7][1], e7, c1); fma2(acc[7][2], e7, c2); fma2(acc[7][3], e7, c3);
        }
#pragma unroll
        for (int tl = 0; tl < 8; tl++) {
#pragma unroll
            for (int j = 0; j < 4; j++) {
                float2 d = upk2(acc[tl][j]);
                int kg = kc0 + tx * 8 + j * 2;
                if (d.x < bval[tl]) { bval[tl] = d.x; bidx[tl] = kg; }
                if (d.y < bval[tl]) { bval[tl] = d.y; bidx[tl] = kg + 1; }
            }
        }
        __syncthreads();
    }
#pragma unroll
    for (int tl = 0; tl < 8; tl++) {
        redv[(ty * 8 + tl) * 16 + tx] = bval[tl];
        redi[(ty * 8 + tl) * 16 + tx] = bidx[tl];
    }
    __syncthreads();
    if (tid < 128) {
        float bv = 3.4028235e38f; int bi = 0x7fffffff;
#pragma unroll
        for (int j = 0; j < 16; j++) {
            float v = redv[tid * 16 + j]; int i = redi[tid * 16 + j];
            if (v < bv || (v == bv && i < bi)) { bv = v; bi = i; }
        }
        scode[tid] = bi;
        out[O_CODES + (long long)b * Tt + t0 + tid] = (float)bi;
    }
    __syncthreads();

    {
        int t = tid & 127, og = tid >> 7;
        int code = scode[t];
        const float* cbrow = cb + (long long)code * CC + og * 32;
        long long xb2 = O_XPROJ + (long long)b * (CC * Tt) + t0 + t;
        long long qb2 = O_QPROJ + (long long)b * (CC * Tt) + t0 + t;
        float ls = 0.f;
#pragma unroll
        for (int j = 0; j < 32; j++) {
            long long ro = (long long)(og * 32 + j) * Tt;
            float xp = out[xb2 + ro];
            float q  = cbrow[j];
            float d  = q - xp;
            out[qb2 + ro] = xp + d;
            ls += d * d;
        }
        __syncthreads();
        redv[tid] = ls; __syncthreads();
        for (int off = 128; off > 0; off >>= 1) {
            if (tid < off) redv[tid] += redv[tid + off];
            __syncthreads();
        }
        if (tid == 0) g_lpart[blockIdx.y * gridDim.x + blockIdx.x] = (double)redv[0];
    }
}

// ---------------- final loss reduction (256 partials) ----------------
__global__ __launch_bounds__(256) void k_loss(float* __restrict__ out)
{
    __shared__ double sb[256];
    int tid = threadIdx.x;
    sb[tid] = g_lpart[tid];
    __syncthreads();
    for (int off = 128; off > 0; off >>= 1) {
        if (tid < off) sb[tid] += sb[tid + off];
        __syncthreads();
    }
    if (tid == 0) {
        float l = (float)(sb[0] / (double)(16.0 * 64.0 * 2048.0));
        out[O_CBL] = l;
        out[O_CML] = l;
    }
}

extern "C" void kernel_launch(void* const* d_in, const int* in_sizes, int n_in,
                              void* d_out, int out_size) {
    (void)in_sizes; (void)n_in; (void)out_size;
    const float* x    = (const float*)d_in[0];
    const float* v_in = (const float*)d_in[1];
    const float* g_in = (const float*)d_in[2];
    const float* v_out= (const float*)d_in[3];
    const float* g_out= (const float*)d_in[4];
    const float* cb   = (const float*)d_in[5];
    float* out = (float*)d_out;

    cudaFuncSetAttribute(k_dist, cudaFuncAttributeMaxDynamicSharedMemorySize, SMEM_DIST);

    k_prep_win<<<64, 256>>>(v_in, g_in);
    k_prep_wout<<<128, 256>>>(v_out, g_out);
    k_prep_cb<<<512, 256>>>(cb);

    float* winp; cudaGetSymbolAddress((void**)&winp, g_Win);

    // WC = codebook @ W_out^T : 64 code-tiles x 8 o-tiles = 512 blocks (overlaps xproj in order)
    k_wc<<<dim3(64, 8), 256>>>(cb);

    // x_proj = W_in @ x : per-b 64x2048, K=1024
    k_gemm64<true><<<dim3(16, 16, 1), 256>>>(winp, CE, 0ll,
                                             x, (long long)CE * Tt,
                                             out + O_XPROJ, (long long)CC * Tt, 0ll);

    // codes / qproj / loss partials : 16 t-tiles x 16 b
    k_dist<<<dim3(16, 16), 256, SMEM_DIST>>>(cb, out);
    k_loss<<<1, 256>>>(out);

    // quantized via gather from WC : 16 t-tiles x 16 b
    k_gather<<<dim3(16, 16), 256>>>(out);
}

// round 14
// speedup vs baseline: 1.3059x; 1.2362x over previous
#include <cuda_runtime.h>
#include <cuda_bf16.h>

typedef unsigned long long u64;
typedef unsigned int u32;
typedef unsigned short u16;

static constexpr int Bb = 16;
static constexpr int CE = 1024;
static constexpr int Tt = 2048;
static constexpr int CC = 64;
static constexpr int Kk = 4096;

static constexpr long long O_CODES = 0;
static constexpr long long O_QUANT = 32768;
static constexpr long long N_QUANT = (long long)Bb * CE * Tt;    // 33554432
static constexpr long long O_CBL   = O_QUANT + N_QUANT;           // 33587200
static constexpr long long O_CML   = O_CBL + 1;
static constexpr long long O_XPROJ = O_CML + 1;                   // 33587202 (even -> 8B aligned)
static constexpr long long N_XP    = (long long)Bb * CC * Tt;     // 2097152
static constexpr long long O_QPROJ = O_XPROJ + N_XP;              // 35684354 (even)

// scratch (static device globals; no runtime allocation)
__device__ __align__(16) float  g_Win[CC * CE];
__device__ __align__(16) float  g_Wout[CE * CC];
__device__ __align__(16) float  g_cbTr[Kk * CC];     // (-2 * normalized codebook), row-major [k][o]
__device__ __align__(16) float  g_cbn2[Kk];          // ||cb_n||^2
__device__ __align__(16) __nv_bfloat16 g_cbE[Kk * 192];  // B ext rows: [c_hi(64) | c_hi(64) | c_lo(64)]
__device__ __align__(16) float  g_WC[Kk * CE];       // WC[k][o] = cb[k,:] . W_out[o,:]
__device__ double g_lpart[256];

__device__ __forceinline__ u64 pk2(float lo, float hi) {
    u64 r; asm("mov.b64 %0, {%1, %2};" : "=l"(r) : "f"(lo), "f"(hi)); return r;
}
__device__ __forceinline__ void fma2(u64 &d, u64 a, u64 b) {
    asm("fma.rn.f32x2 %0, %1, %2, %0;" : "+l"(d) : "l"(a), "l"(b));
}
__device__ __forceinline__ unsigned s2u(const void* p) {
    return (unsigned)__cvta_generic_to_shared(p);
}
__device__ __forceinline__ void cp16(unsigned s, const void* g) {
    asm volatile("cp.async.cg.shared.global [%0], [%1], 16;" :: "r"(s), "l"(g));
}
__device__ __forceinline__ void cpcommit() { asm volatile("cp.async.commit_group;"); }
__device__ __forceinline__ void cpwait1()  { asm volatile("cp.async.wait_group 1;"); }

// ---- warp-level tensor-core helpers (standard PTX, no 'a'-target needed) ----
__device__ __forceinline__ void ldsm4(u32* r, u32 addr) {
    asm volatile("ldmatrix.sync.aligned.m8n8.x4.shared.b16 {%0,%1,%2,%3}, [%4];"
        : "=r"(r[0]), "=r"(r[1]), "=r"(r[2]), "=r"(r[3]) : "r"(addr));
}
__device__ __forceinline__ void ldsm2(u32& r0, u32& r1, u32 addr) {
    asm volatile("ldmatrix.sync.aligned.m8n8.x2.shared.b16 {%0,%1}, [%2];"
        : "=r"(r0), "=r"(r1) : "r"(addr));
}
__device__ __forceinline__ void mma16816(float* d, const u32* a, const u32* b) {
    asm("mma.sync.aligned.m16n8k16.row.col.f32.bf16.bf16.f32 "
        "{%0,%1,%2,%3}, {%4,%5,%6,%7}, {%8,%9}, {%0,%1,%2,%3};"
        : "+f"(d[0]), "+f"(d[1]), "+f"(d[2]), "+f"(d[3])
        : "r"(a[0]), "r"(a[1]), "r"(a[2]), "r"(a[3]), "r"(b[0]), "r"(b[1]));
}

// ---------------- prep: weight-norm W_in ----------------
__global__ __launch_bounds__(256) void k_prep_win(const float* __restrict__ v_in,
                                                  const float* __restrict__ g_in)
{
    __shared__ float sb[256];
    __shared__ float snorm;
    int o = blockIdx.x, tid = threadIdx.x;
    float s = 0.f;
#pragma unroll
    for (int j = 0; j < 4; j++) { float v = v_in[o * CE + tid + j * 256]; s += v * v; }
    sb[tid] = s; __syncthreads();
    for (int off = 128; off > 0; off >>= 1) { if (tid < off) sb[tid] += sb[tid + off]; __syncthreads(); }
    if (tid == 0) snorm = __fsqrt_rn(sb[0]);
    __syncthreads();
    float n = snorm, g = g_in[o];
#pragma unroll
    for (int j = 0; j < 4; j++) {
        int i = tid + j * 256;
        g_Win[o * CE + i] = __fdiv_rn(g * v_in[o * CE + i], n);
    }
}

// ---------------- prep: weight-norm W_out ----------------
__global__ __launch_bounds__(256) void k_prep_wout(const float* __restrict__ v_out,
                                                   const float* __restrict__ g_out)
{
    int gw = (blockIdx.x * 256 + threadIdx.x) >> 5;
    int l = threadIdx.x & 31;
    float a = v_out[gw * CC + l], b = v_out[gw * CC + l + 32];
    float s = a * a + b * b;
#pragma unroll
    for (int off = 16; off; off >>= 1) s += __shfl_xor_sync(0xffffffffu, s, off);
    float n = __fsqrt_rn(s), g = g_out[gw];
    g_Wout[gw * CC + l]      = __fdiv_rn(g * a, n);
    g_Wout[gw * CC + l + 32] = __fdiv_rn(g * b, n);
}

// ---------------- prep: codebook -> cbTr (-2x), cbn2, bf16 ext rows ----------------
__global__ __launch_bounds__(256) void k_prep_cb(const float* __restrict__ cb)
{
    int k = (blockIdx.x * 256 + threadIdx.x) >> 5;
    int l = threadIdx.x & 31;
    float a = cb[k * CC + l], b = cb[k * CC + l + 32];
    float s = a * a + b * b;
#pragma unroll
    for (int off = 16; off; off >>= 1) s += __shfl_xor_sync(0xffffffffu, s, off);
    float n = fmaxf(__fsqrt_rn(s), 1e-12f);
    float ca = __fdiv_rn(a, n), cbv = __fdiv_rn(b, n);
    float v1 = -2.f * ca, v2 = -2.f * cbv;
    g_cbTr[k * CC + l]      = v1;
    g_cbTr[k * CC + l + 32] = v2;
    __nv_bfloat16 h1 = __float2bfloat16(v1);
    __nv_bfloat16 lo1 = __float2bfloat16(v1 - __bfloat162float(h1));
    __nv_bfloat16 h2 = __float2bfloat16(v2);
    __nv_bfloat16 lo2 = __float2bfloat16(v2 - __bfloat162float(h2));
    __nv_bfloat16* row = g_cbE + (long long)k * 192;
    row[l]            = h1;  row[l + 32]       = h2;
    row[64 + l]       = h1;  row[64 + l + 32]  = h2;
    row[128 + l]      = lo1; row[128 + l + 32] = lo2;
    float s2 = ca * ca + cbv * cbv;
#pragma unroll
    for (int off = 16; off; off >>= 1) s2 += __shfl_xor_sync(0xffffffffu, s2, off);
    if (l == 0) g_cbn2[k] = s2;
}

// ---------------- WC = codebook @ W_out^T ----------------
__global__ __launch_bounds__(256) void k_wc(const float* __restrict__ cb)
{
    __shared__ __align__(16) float CBt[64][68];
    __shared__ __align__(16) float WT[64][132];
    int k0 = blockIdx.x * 64;
    int o0 = blockIdx.y * 128;
    int tid = threadIdx.x;
    int to = tid >> 4, tt = tid & 15;

#pragma unroll
    for (int it = 0; it < 4; it++) {
        int rr = tid + it * 256;
        int code = rr >> 4, q = rr & 15;
        float4 v = *(const float4*)&cb[(long long)(k0 + code) * CC + q * 4];
        CBt[q * 4 + 0][code] = v.x; CBt[q * 4 + 1][code] = v.y;
        CBt[q * 4 + 2][code] = v.z; CBt[q * 4 + 3][code] = v.w;
    }
#pragma unroll
    for (int it = 0; it < 8; it++) {
        int rr = tid + it * 256;
        int o = rr >> 4, q = rr & 15;
        float4 v = *(const float4*)&g_Wout[(long long)(o0 + o) * CC + q * 4];
        WT[q * 4 + 0][o] = v.x; WT[q * 4 + 1][o] = v.y;
        WT[q * 4 + 2][o] = v.z; WT[q * 4 + 3][o] = v.w;
    }
    __syncthreads();

    u64 acc[4][4];
#pragma unroll
    for (int i = 0; i < 4; i++)
#pragma unroll
        for (int j = 0; j < 4; j++) acc[i][j] = 0ull;

#pragma unroll 8
    for (int i = 0; i < 64; i++) {
        float4 w  = *(const float4*)&CBt[i][to * 4];
        float4 xa = *(const float4*)&WT[i][tt * 4];
        float4 xb = *(const float4*)&WT[i][64 + tt * 4];
        u64 xa0 = pk2(xa.x, xa.y), xa1 = pk2(xa.z, xa.w);
        u64 xb0 = pk2(xb.x, xb.y), xb1 = pk2(xb.z, xb.w);
        u64 w0 = pk2(w.x, w.x), w1 = pk2(w.y, w.y), w2 = pk2(w.z, w.z), w3 = pk2(w.w, w.w);
        fma2(acc[0][0], w0, xa0); fma2(acc[0][1], w0, xa1); fma2(acc[0][2], w0, xb0); fma2(acc[0][3], w0, xb1);
        fma2(acc[1][0], w1, xa0); fma2(acc[1][1], w1, xa1); fma2(acc[1][2], w1, xb0); fma2(acc[1][3], w1, xb1);
        fma2(acc[2][0], w2, xa0); fma2(acc[2][1], w2, xa1); fma2(acc[2][2], w2, xb0); fma2(acc[2][3], w2, xb1);
        fma2(acc[3][0], w3, xa0); fma2(acc[3][1], w3, xa1); fma2(acc[3][2], w3, xb0); fma2(acc[3][3], w3, xb1);
    }
#pragma unroll
    for (int oj = 0; oj < 4; oj++) {
        float* row = &g_WC[(long long)(k0 + to * 4 + oj) * CE + o0];
        *(u64*)&row[tt * 4]          = acc[oj][0];
        *(u64*)&row[tt * 4 + 2]      = acc[oj][1];
        *(u64*)&row[64 + tt * 4]     = acc[oj][2];
        *(u64*)&row[64 + tt * 4 + 2] = acc[oj][3];
    }
}

// ---------------- gather: quantized[b,o,t] = WC[code[b,t]][o] ----------------
__global__ __launch_bounds__(256) void k_gather(float* __restrict__ out)
{
    __shared__ __align__(16) float Tile[64 * 132];
    __shared__ int scode[128];
    int b = blockIdx.y, tid = threadIdx.x;
    long long t0 = (long long)blockIdx.x * 128;

    if (tid < 128) scode[tid] = (int)out[O_CODES + (long long)b * Tt + t0 + tid];
    __syncthreads();

    for (int oc = 0; oc < 16; oc++) {
#pragma unroll
        for (int it = 0; it < 8; it++) {
            int rr = tid + it * 256;
            int t = rr >> 4, q = rr & 15;
            float4 v = *(const float4*)&g_WC[(long long)scode[t] * CE + oc * 64 + q * 4];
            Tile[(q * 4 + 0) * 132 + t] = v.x;
            Tile[(q * 4 + 1) * 132 + t] = v.y;
            Tile[(q * 4 + 2) * 132 + t] = v.z;
            Tile[(q * 4 + 3) * 132 + t] = v.w;
        }
        __syncthreads();
#pragma unroll
        for (int it = 0; it < 8; it++) {
            int rr = tid + it * 256;
            int o = rr >> 5, t4 = rr & 31;
            *(float4*)&out[O_QUANT + (long long)b * CE * Tt + (long long)(oc * 64 + o) * Tt + t0 + t4 * 4]
                = *(const float4*)&Tile[o * 132 + t4 * 4];
        }
        __syncthreads();
    }
}

// ---------------- gemm (xproj): Out[64 x 128t] = W[64 x K] @ X[K x 128t] ----------------
template<bool XALN16>
__global__ __launch_bounds__(256, 2) void k_gemm64(const float* __restrict__ W, int K,
                                                   const float* __restrict__ X, long long XyS,
                                                   float* __restrict__ O, long long OyS)
{
    __shared__ __align__(16) float Ws[32][68];
    __shared__ __align__(16) float Xs[32][128];
    const float* Xp = X + (long long)blockIdx.y * XyS;
    float* Op = O + (long long)blockIdx.y * OyS + (long long)blockIdx.x * 128;
    int tid = threadIdx.x;
    int to = tid >> 4, tt = tid & 15;
    long long t0 = (long long)blockIdx.x * 128;

    u64 acc[4][4];
#pragma unroll
    for (int i = 0; i < 4; i++)
#pragma unroll
        for (int j = 0; j < 4; j++) acc[i][j] = 0ull;

    for (int kc = 0; kc < K; kc += 32) {
#pragma unroll
        for (int it = 0; it < 2; it++) {
            int rr = tid + it * 256;
            int o = rr >> 3, kq = rr & 7;
            float4 w = *(const float4*)&W[(long long)o * K + kc + kq * 4];
            Ws[kq * 4 + 0][o] = w.x; Ws[kq * 4 + 1][o] = w.y;
            Ws[kq * 4 + 2][o] = w.z; Ws[kq * 4 + 3][o] = w.w;
        }
#pragma unroll
        for (int it = 0; it < 4; it++) {
            int rr = tid + it * 256;
            int i = rr >> 5, t4 = rr & 31;
            long long gidx = (long long)(kc + i) * Tt + t0 + t4 * 4;
            if (XALN16) {
                *(float4*)&Xs[i][t4 * 4] = *(const float4*)&Xp[gidx];
            } else {
                const u64* p = (const u64*)&Xp[gidx];
                *(u64*)&Xs[i][t4 * 4]     = p[0];
                *(u64*)&Xs[i][t4 * 4 + 2] = p[1];
            }
        }
        __syncthreads();
        float4 wn  = *(const float4*)&Ws[0][to * 4];
        float4 xan = *(const float4*)&Xs[0][tt * 4];
        float4 xbn = *(const float4*)&Xs[0][64 + tt * 4];
#pragma unroll 8
        for (int k = 0; k < 32; k++) {
            float4 w = wn, xa = xan, xb = xbn;
            if (k < 31) {
                wn  = *(const float4*)&Ws[k + 1][to * 4];
                xan = *(const float4*)&Xs[k + 1][tt * 4];
                xbn = *(const float4*)&Xs[k + 1][64 + tt * 4];
            }
            u64 xa0 = pk2(xa.x, xa.y), xa1 = pk2(xa.z, xa.w);
            u64 xb0 = pk2(xb.x, xb.y), xb1 = pk2(xb.z, xb.w);
            u64 w0 = pk2(w.x, w.x), w1 = pk2(w.y, w.y), w2 = pk2(w.z, w.z), w3 = pk2(w.w, w.w);
            fma2(acc[0][0], w0, xa0); fma2(acc[0][1], w0, xa1); fma2(acc[0][2], w0, xb0); fma2(acc[0][3], w0, xb1);
            fma2(acc[1][0], w1, xa0); fma2(acc[1][1], w1, xa1); fma2(acc[1][2], w1, xb0); fma2(acc[1][3], w1, xb1);
            fma2(acc[2][0], w2, xa0); fma2(acc[2][1], w2, xa1); fma2(acc[2][2], w2, xb0); fma2(acc[2][3], w2, xb1);
            fma2(acc[3][0], w3, xa0); fma2(acc[3][1], w3, xa1); fma2(acc[3][2], w3, xb0); fma2(acc[3][3], w3, xb1);
        }
        __syncthreads();
    }
#pragma unroll
    for (int oj = 0; oj < 4; oj++) {
        long long rb = (long long)(to * 4 + oj) * Tt;
        *(u64*)&Op[rb + tt * 4]          = acc[oj][0];
        *(u64*)&Op[rb + tt * 4 + 2]      = acc[oj][1];
        *(u64*)&Op[rb + 64 + tt * 4]     = acc[oj][2];
        *(u64*)&Op[rb + 64 + tt * 4 + 2] = acc[oj][3];
    }
}

// ---------------- dist via mma.sync bf16 K-ext split + exact top-2 recheck ----------------
// block = 128 t, 8 warps; 32 chunks of 128 codes, double-buffered cp.async.
// A[t][192] = [e_hi | e_lo | e_hi] bf16 (smem, frag-resident per warp);
// B[k][192] = [c_hi | c_hi | c_lo] (global prebuilt). acc init = ||cb_n||^2
// -> accumulator IS the score. Per-lane top-2 -> merge -> fp32 recheck if gap < 1e-3.
static constexpr int SM_A  = 0;                       // 128 rows x 400 B = 51200
static constexpr int SM_B  = 51200;                   // 2 stages x 51200 = 102400
static constexpr int SM_CC = 153600;                  // 2 x 128 floats = 1024
static constexpr int SM_ES = 154624;                  // 64 x 132 floats = 33792
static constexpr int SM_MV = 188416;                  // mv1/mi1/mv2/mi2: 4 x 2048
static constexpr int SM_SC = 196608;                  // 128 ints
static constexpr int SMEM_DIST = 197120;

__global__ __launch_bounds__(256) void k_dist(const float* __restrict__ cb,
                                              float* __restrict__ out)
{
    extern __shared__ __align__(1024) char smc[];
    __nv_bfloat16* As = (__nv_bfloat16*)(smc + SM_A);
    float* ccB  = (float*)(smc + SM_CC);
    float* Es   = (float*)(smc + SM_ES);
    float* mv1  = (float*)(smc + SM_MV);
    int*   mi1  = (int*)(smc + SM_MV + 2048);
    float* mv2  = (float*)(smc + SM_MV + 4096);
    int*   mi2  = (int*)(smc + SM_MV + 6144);
    int*   scode= (int*)(smc + SM_SC);

    int b = blockIdx.y, tid = threadIdx.x;
    int wid = tid >> 5, lane = tid & 31;
    long long t0 = (long long)blockIdx.x * 128;
    const long long xbase = O_XPROJ + (long long)b * (CC * Tt) + t0;

    // ---- load x_proj tile (8B-aligned) into Es [o][132] ----
#pragma unroll
    for (int it = 0; it < 16; it++) {
        int rr = tid + it * 256;
        int o = rr >> 6, t2 = rr & 63;
        *(u64*)&Es[o * 132 + t2 * 2] = *(const u64*)&out[xbase + (long long)o * Tt + t2 * 2];
    }
    __syncthreads();
    float* den = mv1;                                 // temp use before merge phase
    if (tid < 128) {
        float s = 0.f;
#pragma unroll 8
        for (int o = 0; o < 64; o++) { float v = Es[o * 132 + tid]; s += v * v; }
        den[tid] = fmaxf(__fsqrt_rn(s), 1e-12f);
    }
    __syncthreads();
    // normalize + build A ext rows
#pragma unroll
    for (int it = 0; it < 32; it++) {
        int rr = tid + it * 256;
        int t = rr >> 6, o = rr & 63;
        float e = __fdiv_rn(Es[o * 132 + t], den[t]);
        Es[o * 132 + t] = e;
        __nv_bfloat16 h = __float2bfloat16(e);
        __nv_bfloat16 l = __float2bfloat16(e - __bfloat162float(h));
        __nv_bfloat16* Ar = As + t * 200;
        Ar[o] = h; Ar[64 + o] = l; Ar[128 + o] = h;
    }
    __syncthreads();

    // ---- A fragments: 12 k-steps x 4 regs, resident for all chunks ----
    u32 afr[12][4];
    {
        int m0 = wid * 16;
        u32 arow = (u32)(m0 + (lane & 15));
        u32 acolb = (u32)((lane >> 4) * 16);          // +8 elems = 16 bytes
#pragma unroll
        for (int ks = 0; ks < 12; ks++)
            ldsm4(afr[ks], s2u(smc + SM_A + arow * 400 + ks * 32 + acolb));
    }

    const float FINF = 3.4028235e38f;
    float t1vA = FINF, t2vA = FINF, t1vB = FINF, t2vB = FINF;
    int   t1iA = 0x7fffffff, t2iA = 0x7fffffff, t1iB = 0x7fffffff, t2iB = 0x7fffffff;

    auto loadB = [&](int st, int kc0) {
        char* Bd = smc + SM_B + st * 51200;
        const char* gs = (const char*)g_cbE + (long long)kc0 * 384;
#pragma unroll
        for (int it = 0; it < 12; it++) {
            int i = tid + it * 256;                   // 3072 = 128 rows x 24 segs
            int row = i / 24, seg = i - row * 24;
            cp16(s2u(Bd + row * 400 + seg * 16), gs + row * 384 + seg * 16);
        }
        if (tid < 32) cp16(s2u((char*)(ccB + st * 128) + tid * 16), (const char*)(g_cbn2 + kc0) + tid * 16);
    };
    auto upd = [](float v, int kg, float& v1, int& i1, float& v2, int& i2) {
        if (v < v2) {
            if (v < v1) { v2 = v1; i2 = i1; v1 = v; i1 = kg; }
            else        { v2 = v; i2 = kg; }
        }
    };

    loadB(0, 0); cpcommit();
    for (int ch = 0; ch < 32; ch++) {
        if (ch + 1 < 32) loadB((ch + 1) & 1, (ch + 1) * 128);
        cpcommit(); cpwait1(); __syncthreads();
        const float* ccs = ccB + (ch & 1) * 128;
        char* Bd = smc + SM_B + (ch & 1) * 51200;
        int kc0 = ch * 128;
        u32 brow = (u32)(lane & 7);
        u32 bselb = (u32)(((lane >> 3) & 1) * 16);
        int col = 2 * (lane & 3);

#pragma unroll
        for (int ntg = 0; ntg < 16; ntg += 4) {
            float d[4][4];
#pragma unroll
            for (int j = 0; j < 4; j++) {
                int n0 = (ntg + j) * 8;
                float c0 = ccs[n0 + col], c1 = ccs[n0 + col + 1];
                d[j][0] = c0; d[j][1] = c1; d[j][2] = c0; d[j][3] = c1;
            }
            u32 bc[4][2];
#pragma unroll
            for (int j = 0; j < 4; j++)
                ldsm2(bc[j][0], bc[j][1], s2u(Bd + ((ntg + j) * 8 + brow) * 400 + bselb));
#pragma unroll
            for (int ks = 0; ks < 12; ks++) {
                u32 bn[4][2];
                if (ks < 11) {
#pragma unroll
                    for (int j = 0; j < 4; j++)
                        ldsm2(bn[j][0], bn[j][1], s2u(Bd + ((ntg + j) * 8 + brow) * 400 + (ks + 1) * 32 + bselb));
                }
#pragma unroll
                for (int j = 0; j < 4; j++) mma16816(d[j], afr[ks], bc[j]);
                if (ks < 11) {
#pragma unroll
                    for (int j = 0; j < 4; j++) { bc[j][0] = bn[j][0]; bc[j][1] = bn[j][1]; }
                }
            }
#pragma unroll
            for (int j = 0; j < 4; j++) {
                int kg = kc0 + (ntg + j) * 8 + col;
                upd(d[j][0], kg,     t1vA, t1iA, t2vA, t2iA);
                upd(d[j][1], kg + 1, t1vA, t1iA, t2vA, t2iA);
                upd(d[j][2], kg,     t1vB, t1iB, t2vB, t2iB);
                upd(d[j][3], kg + 1, t1vB, t1iB, t2vB, t2iB);
            }
        }
        __syncthreads();
    }

    // ---- merge per-lane top-2 across the 4 lanes per row ----
    {
        int m0 = wid * 16;
        int r0g = m0 + (lane >> 2), sl = lane & 3;
        mv1[r0g * 4 + sl] = t1vA; mi1[r0g * 4 + sl] = t1iA;
        mv2[r0g * 4 + sl] = t2vA; mi2[r0g * 4 + sl] = t2iA;
        int r1g = r0g + 8;
        mv1[r1g * 4 + sl] = t1vB; mi1[r1g * 4 + sl] = t1iB;
        mv2[r1g * 4 + sl] = t2vB; mi2[r1g * 4 + sl] = t2iB;
    }
    __syncthreads();
    if (tid < 128) {
        float bv1 = FINF, bv2 = FINF; int bi1 = 0x7fffffff, bi2 = 0x7fffffff;
#pragma unroll
        for (int s = 0; s < 4; s++) {
            float v = mv1[tid * 4 + s]; int i = mi1[tid * 4 + s];
            if (v < bv1 || (v == bv1 && i < bi1)) { bv2 = bv1; bi2 = bi1; bv1 = v; bi1 = i; }
            else if (v < bv2 || (v == bv2 && i < bi2)) { bv2 = v; bi2 = i; }
            v = mv2[tid * 4 + s]; i = mi2[tid * 4 + s];
            if (v < bv1 || (v == bv1 && i < bi1)) { bv2 = bv1; bi2 = bi1; bv1 = v; bi1 = i; }
            else if (v < bv2 || (v == bv2 && i < bi2)) { bv2 = v; bi2 = i; }
        }
        int code = bi1;
        if (bv2 - bv1 < 1e-3f) {                      // exact fp32 recheck of near-ties
            float s1 = g_cbn2[bi1], s2 = g_cbn2[bi2];
            const float* r1 = g_cbTr + (long long)bi1 * CC;
            const float* r2 = g_cbTr + (long long)bi2 * CC;
#pragma unroll 8
            for (int o = 0; o < 64; o++) {
                float e = Es[o * 132 + tid];
                s1 = fmaf(r1[o], e, s1);
                s2 = fmaf(r2[o], e, s2);
            }
            if (s2 < s1 || (s2 == s1 && bi2 < bi1)) code = bi2;
        }
        scode[tid] = code;
        out[O_CODES + (long long)b * Tt + t0 + tid] = (float)code;
    }
    __syncthreads();

    // ---- gather q, write quantized_proj = xp + (q - xp), accumulate loss ----
    {
        int t = tid & 127, og = tid >> 7;             // og 0..1 -> 32 o each
        int code = scode[t];
        const float* cbrow = cb + (long long)code * CC + og * 32;
        long long xb2 = O_XPROJ + (long long)b * (CC * Tt) + t0 + t;
        long long qb2 = O_QPROJ + (long long)b * (CC * Tt) + t0 + t;
        float ls = 0.f;
#pragma unroll
        for (int j = 0; j < 32; j++) {
            long long ro = (long long)(og * 32 + j) * Tt;
            float xp = out[xb2 + ro];
            float qv = cbrow[j];
            float dd = qv - xp;
            out[qb2 + ro] = xp + dd;
            ls += dd * dd;
        }
        __syncthreads();
        mv1[tid] = ls; __syncthreads();
        for (int off = 128; off > 0; off >>= 1) {
            if (tid < off) mv1[tid] += mv1[tid + off];
            __syncthreads();
        }
        if (tid == 0) g_lpart[blockIdx.y * gridDim.x + blockIdx.x] = (double)mv1[0];
    }
}

// ---------------- final loss reduction ----------------
__global__ __launch_bounds__(256) void k_loss(float* __restrict__ out)
{
    __shared__ double sb[256];
    int tid = threadIdx.x;
    sb[tid] = g_lpart[tid];
    __syncthreads();
    for (int off = 128; off > 0; off >>= 1) {
        if (tid < off) sb[tid] += sb[tid + off];
        __syncthreads();
    }
    if (tid == 0) {
        float l = (float)(sb[0] / (double)(16.0 * 64.0 * 2048.0));
        out[O_CBL] = l;
        out[O_CML] = l;
    }
}

extern "C" void kernel_launch(void* const* d_in, const int* in_sizes, int n_in,
                              void* d_out, int out_size) {
    (void)in_sizes; (void)n_in; (void)out_size;
    const float* x    = (const float*)d_in[0];
    const float* v_in = (const float*)d_in[1];
    const float* g_in = (const float*)d_in[2];
    const float* v_out= (const float*)d_in[3];
    const float* g_out= (const float*)d_in[4];
    const float* cb   = (const float*)d_in[5];
    float* out = (float*)d_out;

    cudaFuncSetAttribute(k_dist, cudaFuncAttributeMaxDynamicSharedMemorySize, SMEM_DIST);

    k_prep_win<<<64, 256>>>(v_in, g_in);
    k_prep_wout<<<128, 256>>>(v_out, g_out);
    k_prep_cb<<<512, 256>>>(cb);

    float* winp; cudaGetSymbolAddress((void**)&winp, g_Win);

    // WC = codebook @ W_out^T
    k_wc<<<dim3(64, 8), 256>>>(cb);

    // x_proj = W_in @ x
    k_gemm64<true><<<dim3(16, 16), 256>>>(winp, CE, x, (long long)CE * Tt,
                                          out + O_XPROJ, (long long)CC * Tt);

    // codes / qproj / loss partials (tensor-core dist)
    k_dist<<<dim3(16, 16), 256, SMEM_DIST>>>(cb, out);
    k_loss<<<1, 256>>>(out);

    // quantized via gather from WC
    k_gather<<<dim3(16, 16), 256>>>(out);
}

// round 15
// speedup vs baseline: 1.5143x; 1.1596x over previous
#include <cuda_runtime.h>
#include <cuda_bf16.h>

typedef unsigned long long u64;
typedef unsigned int u32;

static constexpr int Bb = 16;
static constexpr int CE = 1024;
static constexpr int Tt = 2048;
static constexpr int CC = 64;
static constexpr int Kk = 4096;

static constexpr long long O_CODES = 0;
static constexpr long long O_QUANT = 32768;
static constexpr long long N_QUANT = (long long)Bb * CE * Tt;    // 33554432
static constexpr long long O_CBL   = O_QUANT + N_QUANT;           // 33587200
static constexpr long long O_CML   = O_CBL + 1;
static constexpr long long O_XPROJ = O_CML + 1;                   // 33587202 (even -> 8B aligned)
static constexpr long long N_XP    = (long long)Bb * CC * Tt;     // 2097152
static constexpr long long O_QPROJ = O_XPROJ + N_XP;              // 35684354 (even)

// scratch (static device globals; no runtime allocation)
__device__ __align__(16) float  g_Win[CC * CE];
__device__ __align__(16) float  g_Wout[CE * CC];
__device__ __align__(16) float  g_cbTr[Kk * CC];     // (-2 * normalized codebook), row-major [k][o]
__device__ __align__(16) float  g_cbn2[Kk];          // ||cb_n||^2
__device__ __align__(16) __nv_bfloat16 g_cbE[Kk * 192];  // B ext rows: [c_hi(64) | c_hi(64) | c_lo(64)]
__device__ __align__(16) float  g_WC[Kk * CE];       // WC[k][o] = cb[k,:] . W_out[o,:]
__device__ double g_lpart[128];

__device__ __forceinline__ u64 pk2(float lo, float hi) {
    u64 r; asm("mov.b64 %0, {%1, %2};" : "=l"(r) : "f"(lo), "f"(hi)); return r;
}
__device__ __forceinline__ void fma2(u64 &d, u64 a, u64 b) {
    asm("fma.rn.f32x2 %0, %1, %2, %0;" : "+l"(d) : "l"(a), "l"(b));
}
__device__ __forceinline__ unsigned s2u(const void* p) {
    return (unsigned)__cvta_generic_to_shared(p);
}
__device__ __forceinline__ void cp16(unsigned s, const void* g) {
    asm volatile("cp.async.cg.shared.global [%0], [%1], 16;" :: "r"(s), "l"(g));
}
__device__ __forceinline__ void cpcommit() { asm volatile("cp.async.commit_group;"); }
__device__ __forceinline__ void cpwait1()  { asm volatile("cp.async.wait_group 1;"); }

// ---- warp-level tensor-core helpers (standard PTX) ----
__device__ __forceinline__ void ldsm4(u32* r, u32 addr) {
    asm volatile("ldmatrix.sync.aligned.m8n8.x4.shared.b16 {%0,%1,%2,%3}, [%4];"
        : "=r"(r[0]), "=r"(r[1]), "=r"(r[2]), "=r"(r[3]) : "r"(addr));
}
__device__ __forceinline__ void ldsm2(u32& r0, u32& r1, u32 addr) {
    asm volatile("ldmatrix.sync.aligned.m8n8.x2.shared.b16 {%0,%1}, [%2];"
        : "=r"(r0), "=r"(r1) : "r"(addr));
}
__device__ __forceinline__ void mma16816(float* d, const u32* a, const u32* b) {
    asm("mma.sync.aligned.m16n8k16.row.col.f32.bf16.bf16.f32 "
        "{%0,%1,%2,%3}, {%4,%5,%6,%7}, {%8,%9}, {%0,%1,%2,%3};"
        : "+f"(d[0]), "+f"(d[1]), "+f"(d[2]), "+f"(d[3])
        : "r"(a[0]), "r"(a[1]), "r"(a[2]), "r"(a[3]), "r"(b[0]), "r"(b[1]));
}

// ---------------- prep: weight-norm W_in ----------------
__global__ __launch_bounds__(256) void k_prep_win(const float* __restrict__ v_in,
                                                  const float* __restrict__ g_in)
{
    __shared__ float sb[256];
    __shared__ float snorm;
    int o = blockIdx.x, tid = threadIdx.x;
    float s = 0.f;
#pragma unroll
    for (int j = 0; j < 4; j++) { float v = v_in[o * CE + tid + j * 256]; s += v * v; }
    sb[tid] = s; __syncthreads();
    for (int off = 128; off > 0; off >>= 1) { if (tid < off) sb[tid] += sb[tid + off]; __syncthreads(); }
    if (tid == 0) snorm = __fsqrt_rn(sb[0]);
    __syncthreads();
    float n = snorm, g = g_in[o];
#pragma unroll
    for (int j = 0; j < 4; j++) {
        int i = tid + j * 256;
        g_Win[o * CE + i] = __fdiv_rn(g * v_in[o * CE + i], n);
    }
}

// ---------------- prep: weight-norm W_out ----------------
__global__ __launch_bounds__(256) void k_prep_wout(const float* __restrict__ v_out,
                                                   const float* __restrict__ g_out)
{
    int gw = (blockIdx.x * 256 + threadIdx.x) >> 5;
    int l = threadIdx.x & 31;
    float a = v_out[gw * CC + l], b = v_out[gw * CC + l + 32];
    float s = a * a + b * b;
#pragma unroll
    for (int off = 16; off; off >>= 1) s += __shfl_xor_sync(0xffffffffu, s, off);
    float n = __fsqrt_rn(s), g = g_out[gw];
    g_Wout[gw * CC + l]      = __fdiv_rn(g * a, n);
    g_Wout[gw * CC + l + 32] = __fdiv_rn(g * b, n);
}

// ---------------- prep: codebook -> cbTr (-2x), cbn2, bf16 ext rows ----------------
__global__ __launch_bounds__(256) void k_prep_cb(const float* __restrict__ cb)
{
    int k = (blockIdx.x * 256 + threadIdx.x) >> 5;
    int l = threadIdx.x & 31;
    float a = cb[k * CC + l], b = cb[k * CC + l + 32];
    float s = a * a + b * b;
#pragma unroll
    for (int off = 16; off; off >>= 1) s += __shfl_xor_sync(0xffffffffu, s, off);
    float n = fmaxf(__fsqrt_rn(s), 1e-12f);
    float ca = __fdiv_rn(a, n), cbv = __fdiv_rn(b, n);
    float v1 = -2.f * ca, v2 = -2.f * cbv;
    g_cbTr[k * CC + l]      = v1;
    g_cbTr[k * CC + l + 32] = v2;
    __nv_bfloat16 h1 = __float2bfloat16(v1);
    __nv_bfloat16 lo1 = __float2bfloat16(v1 - __bfloat162float(h1));
    __nv_bfloat16 h2 = __float2bfloat16(v2);
    __nv_bfloat16 lo2 = __float2bfloat16(v2 - __bfloat162float(h2));
    __nv_bfloat16* row = g_cbE + (long long)k * 192;
    row[l]            = h1;  row[l + 32]       = h2;
    row[64 + l]       = h1;  row[64 + l + 32]  = h2;
    row[128 + l]      = lo1; row[128 + l + 32] = lo2;
    float s2 = ca * ca + cbv * cbv;
#pragma unroll
    for (int off = 16; off; off >>= 1) s2 += __shfl_xor_sync(0xffffffffu, s2, off);
    if (l == 0) g_cbn2[k] = s2;
}

// ---------------- WC = codebook @ W_out^T ----------------
__global__ __launch_bounds__(256) void k_wc(const float* __restrict__ cb)
{
    __shared__ __align__(16) float CBt[64][68];
    __shared__ __align__(16) float WT[64][132];
    int k0 = blockIdx.x * 64;
    int o0 = blockIdx.y * 128;
    int tid = threadIdx.x;
    int to = tid >> 4, tt = tid & 15;

#pragma unroll
    for (int it = 0; it < 4; it++) {
        int rr = tid + it * 256;
        int code = rr >> 4, q = rr & 15;
        float4 v = *(const float4*)&cb[(long long)(k0 + code) * CC + q * 4];
        CBt[q * 4 + 0][code] = v.x; CBt[q * 4 + 1][code] = v.y;
        CBt[q * 4 + 2][code] = v.z; CBt[q * 4 + 3][code] = v.w;
    }
#pragma unroll
    for (int it = 0; it < 8; it++) {
        int rr = tid + it * 256;
        int o = rr >> 4, q = rr & 15;
        float4 v = *(const float4*)&g_Wout[(long long)(o0 + o) * CC + q * 4];
        WT[q * 4 + 0][o] = v.x; WT[q * 4 + 1][o] = v.y;
        WT[q * 4 + 2][o] = v.z; WT[q * 4 + 3][o] = v.w;
    }
    __syncthreads();

    u64 acc[4][4];
#pragma unroll
    for (int i = 0; i < 4; i++)
#pragma unroll
        for (int j = 0; j < 4; j++) acc[i][j] = 0ull;

#pragma unroll 8
    for (int i = 0; i < 64; i++) {
        float4 w  = *(const float4*)&CBt[i][to * 4];
        float4 xa = *(const float4*)&WT[i][tt * 4];
        float4 xb = *(const float4*)&WT[i][64 + tt * 4];
        u64 xa0 = pk2(xa.x, xa.y), xa1 = pk2(xa.z, xa.w);
        u64 xb0 = pk2(xb.x, xb.y), xb1 = pk2(xb.z, xb.w);
        u64 w0 = pk2(w.x, w.x), w1 = pk2(w.y, w.y), w2 = pk2(w.z, w.z), w3 = pk2(w.w, w.w);
        fma2(acc[0][0], w0, xa0); fma2(acc[0][1], w0, xa1); fma2(acc[0][2], w0, xb0); fma2(acc[0][3], w0, xb1);
        fma2(acc[1][0], w1, xa0); fma2(acc[1][1], w1, xa1); fma2(acc[1][2], w1, xb0); fma2(acc[1][3], w1, xb1);
        fma2(acc[2][0], w2, xa0); fma2(acc[2][1], w2, xa1); fma2(acc[2][2], w2, xb0); fma2(acc[2][3], w2, xb1);
        fma2(acc[3][0], w3, xa0); fma2(acc[3][1], w3, xa1); fma2(acc[3][2], w3, xb0); fma2(acc[3][3], w3, xb1);
    }
#pragma unroll
    for (int oj = 0; oj < 4; oj++) {
        float* row = &g_WC[(long long)(k0 + to * 4 + oj) * CE + o0];
        *(u64*)&row[tt * 4]          = acc[oj][0];
        *(u64*)&row[tt * 4 + 2]      = acc[oj][1];
        *(u64*)&row[64 + tt * 4]     = acc[oj][2];
        *(u64*)&row[64 + tt * 4 + 2] = acc[oj][3];
    }
}

// ---------------- gather: quantized[b,o,t] = WC[code[b,t]][o] ----------------
__global__ __launch_bounds__(256) void k_gather(float* __restrict__ out)
{
    __shared__ __align__(16) float Tile[64 * 132];
    __shared__ int scode[128];
    int b = blockIdx.y, tid = threadIdx.x;
    long long t0 = (long long)blockIdx.x * 128;

    if (tid < 128) scode[tid] = (int)out[O_CODES + (long long)b * Tt + t0 + tid];
    __syncthreads();

    for (int oc = 0; oc < 16; oc++) {
#pragma unroll
        for (int it = 0; it < 8; it++) {
            int rr = tid + it * 256;
            int t = rr >> 4, q = rr & 15;
            float4 v = *(const float4*)&g_WC[(long long)scode[t] * CE + oc * 64 + q * 4];
            Tile[(q * 4 + 0) * 132 + t] = v.x;
            Tile[(q * 4 + 1) * 132 + t] = v.y;
            Tile[(q * 4 + 2) * 132 + t] = v.z;
            Tile[(q * 4 + 3) * 132 + t] = v.w;
        }
        __syncthreads();
#pragma unroll
        for (int it = 0; it < 8; it++) {
            int rr = tid + it * 256;
            int o = rr >> 5, t4 = rr & 31;
            *(float4*)&out[O_QUANT + (long long)b * CE * Tt + (long long)(oc * 64 + o) * Tt + t0 + t4 * 4]
                = *(const float4*)&Tile[o * 132 + t4 * 4];
        }
        __syncthreads();
    }
}

// ---------------- gemm (xproj): Out[64 x 128t] = W[64 x K] @ X[K x 128t] ----------------
template<bool XALN16>
__global__ __launch_bounds__(256, 2) void k_gemm64(const float* __restrict__ W, int K,
                                                   const float* __restrict__ X, long long XyS,
                                                   float* __restrict__ O, long long OyS)
{
    __shared__ __align__(16) float Ws[32][68];
    __shared__ __align__(16) float Xs[32][128];
    const float* Xp = X + (long long)blockIdx.y * XyS;
    float* Op = O + (long long)blockIdx.y * OyS + (long long)blockIdx.x * 128;
    int tid = threadIdx.x;
    int to = tid >> 4, tt = tid & 15;
    long long t0 = (long long)blockIdx.x * 128;

    u64 acc[4][4];
#pragma unroll
    for (int i = 0; i < 4; i++)
#pragma unroll
        for (int j = 0; j < 4; j++) acc[i][j] = 0ull;

    for (int kc = 0; kc < K; kc += 32) {
#pragma unroll
        for (int it = 0; it < 2; it++) {
            int rr = tid + it * 256;
            int o = rr >> 3, kq = rr & 7;
            float4 w = *(const float4*)&W[(long long)o * K + kc + kq * 4];
            Ws[kq * 4 + 0][o] = w.x; Ws[kq * 4 + 1][o] = w.y;
            Ws[kq * 4 + 2][o] = w.z; Ws[kq * 4 + 3][o] = w.w;
        }
#pragma unroll
        for (int it = 0; it < 4; it++) {
            int rr = tid + it * 256;
            int i = rr >> 5, t4 = rr & 31;
            long long gidx = (long long)(kc + i) * Tt + t0 + t4 * 4;
            if (XALN16) {
                *(float4*)&Xs[i][t4 * 4] = *(const float4*)&Xp[gidx];
            } else {
                const u64* p = (const u64*)&Xp[gidx];
                *(u64*)&Xs[i][t4 * 4]     = p[0];
                *(u64*)&Xs[i][t4 * 4 + 2] = p[1];
            }
        }
        __syncthreads();
        float4 wn  = *(const float4*)&Ws[0][to * 4];
        float4 xan = *(const float4*)&Xs[0][tt * 4];
        float4 xbn = *(const float4*)&Xs[0][64 + tt * 4];
#pragma unroll 8
        for (int k = 0; k < 32; k++) {
            float4 w = wn, xa = xan, xb = xbn;
            if (k < 31) {
                wn  = *(const float4*)&Ws[k + 1][to * 4];
                xan = *(const float4*)&Xs[k + 1][tt * 4];
                xbn = *(const float4*)&Xs[k + 1][64 + tt * 4];
            }
            u64 xa0 = pk2(xa.x, xa.y), xa1 = pk2(xa.z, xa.w);
            u64 xb0 = pk2(xb.x, xb.y), xb1 = pk2(xb.z, xb.w);
            u64 w0 = pk2(w.x, w.x), w1 = pk2(w.y, w.y), w2 = pk2(w.z, w.z), w3 = pk2(w.w, w.w);
            fma2(acc[0][0], w0, xa0); fma2(acc[0][1], w0, xa1); fma2(acc[0][2], w0, xb0); fma2(acc[0][3], w0, xb1);
            fma2(acc[1][0], w1, xa0); fma2(acc[1][1], w1, xa1); fma2(acc[1][2], w1, xb0); fma2(acc[1][3], w1, xb1);
            fma2(acc[2][0], w2, xa0); fma2(acc[2][1], w2, xa1); fma2(acc[2][2], w2, xb0); fma2(acc[2][3], w2, xb1);
            fma2(acc[3][0], w3, xa0); fma2(acc[3][1], w3, xa1); fma2(acc[3][2], w3, xb0); fma2(acc[3][3], w3, xb1);
        }
        __syncthreads();
    }
#pragma unroll
    for (int oj = 0; oj < 4; oj++) {
        long long rb = (long long)(to * 4 + oj) * Tt;
        *(u64*)&Op[rb + tt * 4]          = acc[oj][0];
        *(u64*)&Op[rb + tt * 4 + 2]      = acc[oj][1];
        *(u64*)&Op[rb + 64 + tt * 4]     = acc[oj][2];
        *(u64*)&Op[rb + 64 + tt * 4 + 2] = acc[oj][3];
    }
}

// ---------------- dist v2: 256-t blocks, B-frag shared across 2 rowsets ----------------
// block = 256 t, 8 warps; warp covers rows [w*16,+16) and [128+w*16,+16).
// A[t][192] = [e_hi | e_lo | e_hi] bf16; B[k][192] = [c_hi | c_hi | c_lo] (prebuilt).
// 32 chunks of 128 codes, double-buffered cp.async; acc init = ||cb_n||^2;
// per-lane top-2 (4 sets) -> merge -> fp32 recheck from global when gap < 1e-3.
static constexpr int SM_A  = 0;                       // 256 rows x 400 B = 102400
static constexpr int SM_B  = 102400;                  // 2 stages x 51200
static constexpr int SM_CC = 204800;                  // 2 x 128 floats
static constexpr int SM_DEN= 205824;                  // 256 floats
static constexpr int SM_SC = 206848;                  // 256 ints
static constexpr int SMEM_DIST = 207872;

__global__ __launch_bounds__(256, 1) void k_dist(const float* __restrict__ cb,
                                                 float* __restrict__ out)
{
    extern __shared__ __align__(1024) char smc[];
    float* ccB  = (float*)(smc + SM_CC);
    float* den  = (float*)(smc + SM_DEN);
    int*   scode= (int*)(smc + SM_SC);
    // merge scratch overlaps B (used only after the chunk loop)
    float* mv1  = (float*)(smc + SM_B);
    int*   mi1  = (int*)(smc + SM_B + 4096);
    float* mv2  = (float*)(smc + SM_B + 8192);
    int*   mi2  = (int*)(smc + SM_B + 12288);

    int b = blockIdx.y, tid = threadIdx.x;
    int wid = tid >> 5, lane = tid & 31;
    long long t0 = (long long)blockIdx.x * 256;
    const long long xbase = O_XPROJ + (long long)b * (CC * Tt) + t0;

    // ---- stage x_proj (64 o x 256 t) into B region, compute den, build A ----
    float* stage = (float*)(smc + SM_B);              // [64][260]
#pragma unroll
    for (int it = 0; it < 32; it++) {
        int rr = tid + it * 256;                      // 8192 u64: 64 o x 128 t2
        int o = rr >> 7, t2 = rr & 127;
        *(u64*)&stage[o * 260 + t2 * 2] = *(const u64*)&out[xbase + (long long)o * Tt + t2 * 2];
    }
    __syncthreads();
    {
        float s = 0.f;
#pragma unroll 8
        for (int o = 0; o < 64; o++) { float v = stage[o * 260 + tid]; s += v * v; }
        den[tid] = fmaxf(__fsqrt_rn(s), 1e-12f);
    }
    __syncthreads();
#pragma unroll
    for (int it = 0; it < 64; it++) {
        int rr = tid + it * 256;                      // 16384: 256 t x 64 o
        int t = rr >> 6, o = rr & 63;
        float e = __fdiv_rn(stage[o * 260 + t], den[t]);
        __nv_bfloat16 h = __float2bfloat16(e);
        __nv_bfloat16 l = __float2bfloat16(e - __bfloat162float(h));
        __nv_bfloat16* Ar = (__nv_bfloat16*)(smc + SM_A) + t * 200;
        Ar[o] = h; Ar[64 + o] = l; Ar[128 + o] = h;
    }
    __syncthreads();

    // ---- A fragments: 2 rowsets x 12 k-steps x 4 regs, resident ----
    u32 afr[2][12][4];
#pragma unroll
    for (int rs = 0; rs < 2; rs++) {
        int m0 = rs * 128 + wid * 16;
        u32 arow = (u32)(m0 + (lane & 15));
        u32 acolb = (u32)((lane >> 4) * 16);
#pragma unroll
        for (int ks = 0; ks < 12; ks++)
            ldsm4(afr[rs][ks], s2u(smc + SM_A + arow * 400 + ks * 32 + acolb));
    }

    const float FINF = 3.4028235e38f;
    float t1v[2][2], t2v[2][2]; int t1i[2][2], t2i[2][2];
#pragma unroll
    for (int rs = 0; rs < 2; rs++)
#pragma unroll
        for (int h = 0; h < 2; h++) {
            t1v[rs][h] = FINF; t2v[rs][h] = FINF;
            t1i[rs][h] = 0x7fffffff; t2i[rs][h] = 0x7fffffff;
        }

    auto loadB = [&](int st, int kc0) {
        char* Bd = smc + SM_B + st * 51200;
        const char* gs = (const char*)g_cbE + (long long)kc0 * 384;
#pragma unroll
        for (int it = 0; it < 12; it++) {
            int i = tid + it * 256;                   // 3072 = 128 rows x 24 segs
            int row = i / 24, seg = i - row * 24;
            cp16(s2u(Bd + row * 400 + seg * 16), gs + row * 384 + seg * 16);
        }
        if (tid < 32) cp16(s2u((char*)(ccB + st * 128) + tid * 16), (const char*)(g_cbn2 + kc0) + tid * 16);
    };
    auto upd = [](float v, int kg, float& v1, int& i1, float& v2, int& i2) {
        if (v < v2) {
            if (v < v1) { v2 = v1; i2 = i1; v1 = v; i1 = kg; }
            else        { v2 = v; i2 = kg; }
        }
    };

    loadB(0, 0); cpcommit();
    for (int ch = 0; ch < 32; ch++) {
        if (ch + 1 < 32) loadB((ch + 1) & 1, (ch + 1) * 128);
        cpcommit(); cpwait1(); __syncthreads();
        const float* ccs = ccB + (ch & 1) * 128;
        char* Bd = smc + SM_B + (ch & 1) * 51200;
        int kc0 = ch * 128;
        u32 brow = (u32)(lane & 7);
        u32 bselb = (u32)(((lane >> 3) & 1) * 16);
        int col = 2 * (lane & 3);

#pragma unroll
        for (int nt = 0; nt < 16; nt += 2) {
            float d[4][4];                            // [rs*2 + j][4]
#pragma unroll
            for (int j = 0; j < 2; j++) {
                int n0 = (nt + j) * 8;
                float c0 = ccs[n0 + col], c1 = ccs[n0 + col + 1];
                d[j][0] = c0; d[j][1] = c1; d[j][2] = c0; d[j][3] = c1;
                d[2 + j][0] = c0; d[2 + j][1] = c1; d[2 + j][2] = c0; d[2 + j][3] = c1;
            }
            u32 bc[2][2];
#pragma unroll
            for (int j = 0; j < 2; j++)
                ldsm2(bc[j][0], bc[j][1], s2u(Bd + ((nt + j) * 8 + brow) * 400 + bselb));
#pragma unroll
            for (int ks = 0; ks < 12; ks++) {
                u32 bn[2][2];
                if (ks < 11) {
#pragma unroll
                    for (int j = 0; j < 2; j++)
                        ldsm2(bn[j][0], bn[j][1], s2u(Bd + ((nt + j) * 8 + brow) * 400 + (ks + 1) * 32 + bselb));
                }
                mma16816(d[0], afr[0][ks], bc[0]); mma16816(d[1], afr[0][ks], bc[1]);
                mma16816(d[2], afr[1][ks], bc[0]); mma16816(d[3], afr[1][ks], bc[1]);
                if (ks < 11) {
#pragma unroll
                    for (int j = 0; j < 2; j++) { bc[j][0] = bn[j][0]; bc[j][1] = bn[j][1]; }
                }
            }
#pragma unroll
            for (int j = 0; j < 2; j++) {
                int kg = kc0 + (nt + j) * 8 + col;
                upd(d[j][0], kg,     t1v[0][0], t1i[0][0], t2v[0][0], t2i[0][0]);
                upd(d[j][1], kg + 1, t1v[0][0], t1i[0][0], t2v[0][0], t2i[0][0]);
                upd(d[j][2], kg,     t1v[0][1], t1i[0][1], t2v[0][1], t2i[0][1]);
                upd(d[j][3], kg + 1, t1v[0][1], t1i[0][1], t2v[0][1], t2i[0][1]);
                upd(d[2 + j][0], kg,     t1v[1][0], t1i[1][0], t2v[1][0], t2i[1][0]);
                upd(d[2 + j][1], kg + 1, t1v[1][0], t1i[1][0], t2v[1][0], t2i[1][0]);
                upd(d[2 + j][2], kg,     t1v[1][1], t1i[1][1], t2v[1][1], t2i[1][1]);
                upd(d[2 + j][3], kg + 1, t1v[1][1], t1i[1][1], t2v[1][1], t2i[1][1]);
            }
        }
        __syncthreads();
    }

    // ---- merge per-lane top-2 across the 4 lanes per row ----
#pragma unroll
    for (int rs = 0; rs < 2; rs++)
#pragma unroll
        for (int h = 0; h < 2; h++) {
            int row = rs * 128 + wid * 16 + h * 8 + (lane >> 2);
            int sl = lane & 3;
            mv1[row * 4 + sl] = t1v[rs][h]; mi1[row * 4 + sl] = t1i[rs][h];
            mv2[row * 4 + sl] = t2v[rs][h]; mi2[row * 4 + sl] = t2i[rs][h];
        }
    __syncthreads();
    {
        float bv1 = FINF, bv2 = FINF; int bi1 = 0x7fffffff, bi2 = 0x7fffffff;
#pragma unroll
        for (int s = 0; s < 4; s++) {
            float v = mv1[tid * 4 + s]; int i = mi1[tid * 4 + s];
            if (v < bv1 || (v == bv1 && i < bi1)) { bv2 = bv1; bi2 = bi1; bv1 = v; bi1 = i; }
            else if (v < bv2 || (v == bv2 && i < bi2)) { bv2 = v; bi2 = i; }
            v = mv2[tid * 4 + s]; i = mi2[tid * 4 + s];
            if (v < bv1 || (v == bv1 && i < bi1)) { bv2 = bv1; bi2 = bi1; bv1 = v; bi1 = i; }
            else if (v < bv2 || (v == bv2 && i < bi2)) { bv2 = v; bi2 = i; }
        }
        int code = bi1;
        if (bv2 - bv1 < 1e-3f) {                      // exact fp32 recheck from global
            float dn = den[tid];
            float s1 = g_cbn2[bi1], s2 = g_cbn2[bi2];
            const float* r1 = g_cbTr + (long long)bi1 * CC;
            const float* r2 = g_cbTr + (long long)bi2 * CC;
#pragma unroll 8
            for (int o = 0; o < 64; o++) {
                float e = __fdiv_rn(out[xbase + (long long)o * Tt + tid], dn);
                s1 = fmaf(r1[o], e, s1);
                s2 = fmaf(r2[o], e, s2);
            }
            if (s2 < s1 || (s2 == s1 && bi2 < bi1)) code = bi2;
        }
        scode[tid] = code;
        out[O_CODES + (long long)b * Tt + t0 + tid] = (float)code;
    }
    __syncthreads();

    // ---- gather q, write quantized_proj = xp + (q - xp), accumulate loss ----
    {
        int code = scode[tid];
        const float* cbrow = cb + (long long)code * CC;
        long long xb2 = xbase + tid;
        long long qb2 = O_QPROJ + (long long)b * (CC * Tt) + t0 + tid;
        float ls = 0.f;
#pragma unroll 8
        for (int j = 0; j < 64; j++) {
            long long ro = (long long)j * Tt;
            float xp = out[xb2 + ro];
            float qv = cbrow[j];
            float dd = qv - xp;
            out[qb2 + ro] = xp + dd;
            ls += dd * dd;
        }
        __syncthreads();
        mv1[tid] = ls; __syncthreads();
        for (int off = 128; off > 0; off >>= 1) {
            if (tid < off) mv1[tid] += mv1[tid + off];
            __syncthreads();
        }
        if (tid == 0) g_lpart[blockIdx.y * gridDim.x + blockIdx.x] = (double)mv1[0];
    }
}

// ---------------- final loss reduction (128 partials) ----------------
__global__ __launch_bounds__(128) void k_loss(float* __restrict__ out)
{
    __shared__ double sb[128];
    int tid = threadIdx.x;
    sb[tid] = g_lpart[tid];
    __syncthreads();
    for (int off = 64; off > 0; off >>= 1) {
        if (tid < off) sb[tid] += sb[tid + off];
        __syncthreads();
    }
    if (tid == 0) {
        float l = (float)(sb[0] / (double)(16.0 * 64.0 * 2048.0));
        out[O_CBL] = l;
        out[O_CML] = l;
    }
}

extern "C" void kernel_launch(void* const* d_in, const int* in_sizes, int n_in,
                              void* d_out, int out_size) {
    (void)in_sizes; (void)n_in; (void)out_size;
    const float* x    = (const float*)d_in[0];
    const float* v_in = (const float*)d_in[1];
    const float* g_in = (const float*)d_in[2];
    const float* v_out= (const float*)d_in[3];
    const float* g_out= (const float*)d_in[4];
    const float* cb   = (const float*)d_in[5];
    float* out = (float*)d_out;

    cudaFuncSetAttribute(k_dist, cudaFuncAttributeMaxDynamicSharedMemorySize, SMEM_DIST);

    k_prep_win<<<64, 256>>>(v_in, g_in);
    k_prep_wout<<<128, 256>>>(v_out, g_out);
    k_prep_cb<<<512, 256>>>(cb);

    float* winp; cudaGetSymbolAddress((void**)&winp, g_Win);

    // WC = codebook @ W_out^T
    k_wc<<<dim3(64, 8), 256>>>(cb);

    // x_proj = W_in @ x
    k_gemm64<true><<<dim3(16, 16), 256>>>(winp, CE, x, (long long)CE * Tt,
                                          out + O_XPROJ, (long long)CC * Tt);

    // codes / qproj / loss partials (tensor-core dist, 256-t blocks, single wave)
    k_dist<<<dim3(8, 16), 256, SMEM_DIST>>>(cb, out);
    k_loss<<<1, 128>>>(out);

    // quantized via gather from WC
    k_gather<<<dim3(16, 16), 256>>>(out);
}